// round 2
// baseline (speedup 1.0000x reference)
#include <cuda_runtime.h>
#include <cuda_bf16.h>
#include <cstdint>

#define B_    16
#define NSEQ  1168
#define H_    8
#define DH    32
#define C_    256
#define NPAD  1280
#define MROWS (B_*NSEQ)   // 18688 = 146*128

// ---------------- scratch (device globals; no runtime alloc) ----------------
__device__ float          g_qkv[(size_t)MROWS * 768];          // 57.4 MB
__device__ __nv_bfloat16  g_bias[(size_t)H_ * NSEQ * NPAD];    // 23.9 MB
__device__ float          g_att[(size_t)MROWS * C_];           // 19.1 MB
__device__ float          g_madd[(size_t)B_ * NSEQ];           // additive mask

// ---------------- helpers ----------------
__device__ __forceinline__ float tf32r(float x) {
    uint32_t u;
    asm("cvt.rna.tf32.f32 %0, %1;" : "=r"(u) : "f"(x));
    return __uint_as_float(u);
}
__device__ __forceinline__ uint32_t pack_bf16(float x, float y) {
    __nv_bfloat162 h = __floats2bfloat162_rn(x, y);
    return *reinterpret_cast<uint32_t*>(&h);
}
__device__ __forceinline__ void mma_tf32(float& d0, float& d1, float& d2, float& d3,
                                         uint32_t a0, uint32_t a1, uint32_t a2, uint32_t a3,
                                         uint32_t b0, uint32_t b1) {
    asm volatile("mma.sync.aligned.m16n8k8.row.col.f32.tf32.tf32.f32 "
                 "{%0,%1,%2,%3},{%4,%5,%6,%7},{%8,%9},{%0,%1,%2,%3};"
                 : "+f"(d0), "+f"(d1), "+f"(d2), "+f"(d3)
                 : "r"(a0), "r"(a1), "r"(a2), "r"(a3), "r"(b0), "r"(b1));
}
__device__ __forceinline__ void mma_bf16(float& d0, float& d1, float& d2, float& d3,
                                         uint32_t a0, uint32_t a1, uint32_t a2, uint32_t a3,
                                         uint32_t b0, uint32_t b1) {
    asm volatile("mma.sync.aligned.m16n8k16.row.col.f32.bf16.bf16.f32 "
                 "{%0,%1,%2,%3},{%4,%5,%6,%7},{%8,%9},{%0,%1,%2,%3};"
                 : "+f"(d0), "+f"(d1), "+f"(d2), "+f"(d3)
                 : "r"(a0), "r"(a1), "r"(a2), "r"(a3), "r"(b0), "r"(b1));
}

// ---------------- 0) mask canonicalization (dtype auto-detect) ----------------
// The reference mask is a JAX bool; the harness may hand it to us as uint8,
// int32 or float32. Detect by byte-lane occupancy (value-based, deterministic):
//   uint8  : nonzero bytes appear at i%4==1
//   float32: 1.0f = 00 00 80 3F -> nonzero only at i%4 in {2,3}
//   int32  : 1    = 01 00 00 00 -> nonzero only at i%4==0
__global__ void mask_kernel(const unsigned char* __restrict__ mraw) {
    __shared__ int s_pos[4];
    if (threadIdx.x < 4) s_pos[threadIdx.x] = 0;
    __syncthreads();
    int loc[4] = {0, 0, 0, 0};
    for (int i = threadIdx.x; i < 4096; i += blockDim.x)
        if (mraw[i]) loc[i & 3] = 1;
    #pragma unroll
    for (int p = 0; p < 4; p++)
        if (loc[p]) atomicOr(&s_pos[p], 1);
    __syncthreads();
    int mode;                 // 0=uint8, 1=int32, 2=float32
    if (s_pos[1]) mode = 0;
    else if (s_pos[2] | s_pos[3]) mode = 2;
    else mode = 1;
    const int total = B_ * NSEQ;
    for (int i = threadIdx.x; i < total; i += blockDim.x) {
        bool m;
        if (mode == 0)      m = mraw[i] != 0;
        else if (mode == 1) m = ((const int*)mraw)[i] != 0;
        else                m = ((const float*)mraw)[i] != 0.f;
        g_madd[i] = m ? -3e38f : 0.f;
    }
}

// ---------------- 1) relative-position bias gather ----------------
__global__ void bias_kernel(const int* __restrict__ rel_index,
                            const float* __restrict__ rpb, int num_rel) {
    int idx = blockIdx.x * blockDim.x + threadIdx.x;
    if (idx >= NSEQ * NPAD) return;
    int i = idx / NPAD;
    int j = idx - i * NPAD;
    if (j < NSEQ) {
        int r = rel_index[i * NSEQ + j];
        #pragma unroll
        for (int h = 0; h < H_; h++)
            g_bias[((size_t)h * NSEQ + i) * NPAD + j] = __float2bfloat16(rpb[h * num_rel + r]);
    } else {
        #pragma unroll
        for (int h = 0; h < H_; h++)
            g_bias[((size_t)h * NSEQ + i) * NPAD + j] = __float2bfloat16(0.f);
    }
}

// ---------------- 2/4) tf32 GEMM: C[M,Nt] = A[M,256] * W[Nt,256]^T (+bias) ----------------
template<bool ADD_BIAS>
__global__ __launch_bounds__(256)
void gemm_tf32(const float* __restrict__ A, const float* __restrict__ W,
               const float* __restrict__ bias, float* __restrict__ Cout, int Ntotal) {
    extern __shared__ float sm[];
    float* As = sm;               // [128][68]
    float* Bs = sm + 128 * 68;    // [128][68]
    const int tid  = threadIdx.x;
    const int warp = tid >> 5, lane = tid & 31;
    const int g = lane >> 2, t = lane & 3;
    const int wm = warp >> 1, wn = warp & 1;
    const int bm = blockIdx.x, bn = blockIdx.y;

    float acc[2][8][4];
    #pragma unroll
    for (int i = 0; i < 2; i++)
        #pragma unroll
        for (int j = 0; j < 8; j++)
            #pragma unroll
            for (int k = 0; k < 4; k++) acc[i][j][k] = 0.f;

    for (int kc = 0; kc < 4; kc++) {
        {
            int r  = tid >> 4;            // 0..15
            int c4 = (tid & 15) * 4;      // 0..60
            const float* Ag = A + ((size_t)(bm * 128 + r)) * 256 + kc * 64 + c4;
            const float* Bg = W + ((size_t)(bn * 128 + r)) * 256 + kc * 64 + c4;
            #pragma unroll
            for (int it = 0; it < 8; it++) {
                float4 av = *(const float4*)(Ag + (size_t)it * 16 * 256);
                float4 bv = *(const float4*)(Bg + (size_t)it * 16 * 256);
                float* ad = &As[(r + it * 16) * 68 + c4];
                float* bd = &Bs[(r + it * 16) * 68 + c4];
                ad[0] = tf32r(av.x); ad[1] = tf32r(av.y); ad[2] = tf32r(av.z); ad[3] = tf32r(av.w);
                bd[0] = tf32r(bv.x); bd[1] = tf32r(bv.y); bd[2] = tf32r(bv.z); bd[3] = tf32r(bv.w);
            }
        }
        __syncthreads();
        #pragma unroll
        for (int ks = 0; ks < 8; ks++) {
            int k0 = ks * 8;
            uint32_t aF[2][4];
            #pragma unroll
            for (int mt = 0; mt < 2; mt++) {
                int m0 = wm * 32 + mt * 16;
                aF[mt][0] = __float_as_uint(As[(m0 + g    ) * 68 + k0 + t    ]);
                aF[mt][1] = __float_as_uint(As[(m0 + g + 8) * 68 + k0 + t    ]);
                aF[mt][2] = __float_as_uint(As[(m0 + g    ) * 68 + k0 + t + 4]);
                aF[mt][3] = __float_as_uint(As[(m0 + g + 8) * 68 + k0 + t + 4]);
            }
            #pragma unroll
            for (int nt = 0; nt < 8; nt++) {
                int n0 = wn * 64 + nt * 8;
                uint32_t b0 = __float_as_uint(Bs[(n0 + g) * 68 + k0 + t    ]);
                uint32_t b1 = __float_as_uint(Bs[(n0 + g) * 68 + k0 + t + 4]);
                mma_tf32(acc[0][nt][0], acc[0][nt][1], acc[0][nt][2], acc[0][nt][3],
                         aF[0][0], aF[0][1], aF[0][2], aF[0][3], b0, b1);
                mma_tf32(acc[1][nt][0], acc[1][nt][1], acc[1][nt][2], acc[1][nt][3],
                         aF[1][0], aF[1][1], aF[1][2], aF[1][3], b0, b1);
            }
        }
        __syncthreads();
    }
    #pragma unroll
    for (int mt = 0; mt < 2; mt++) {
        int r0 = bm * 128 + wm * 32 + mt * 16 + g;
        #pragma unroll
        for (int nt = 0; nt < 8; nt++) {
            int c0 = bn * 128 + wn * 64 + nt * 8 + 2 * t;
            float bb0 = 0.f, bb1 = 0.f;
            if (ADD_BIAS) { bb0 = bias[c0]; bb1 = bias[c0 + 1]; }
            float2 v0 = make_float2(acc[mt][nt][0] + bb0, acc[mt][nt][1] + bb1);
            float2 v1 = make_float2(acc[mt][nt][2] + bb0, acc[mt][nt][3] + bb1);
            *(float2*)&Cout[(size_t)r0       * Ntotal + c0] = v0;
            *(float2*)&Cout[(size_t)(r0 + 8) * Ntotal + c0] = v1;
        }
    }
}

// ---------------- 3) flash attention (bf16 mma, online softmax) ----------------
__global__ __launch_bounds__(256)
void attn_kernel() {
    extern __shared__ char smx[];
    __nv_bfloat16* Ks   = (__nv_bfloat16*)smx;                      // [128][36]  9216 B
    __nv_bfloat16* Vt   = (__nv_bfloat16*)(smx + 9216);             // [32][136]  8704 B
    __nv_bfloat16* Bias = (__nv_bfloat16*)(smx + 9216 + 8704);      // [128][136] 34816 B
    float*         MAdd = (float*)(smx + 9216 + 8704 + 34816);      // [128]      512 B

    const int tid  = threadIdx.x;
    const int warp = tid >> 5, lane = tid & 31;
    const int g = lane >> 2, t = lane & 3;
    const int qt = blockIdx.x, bh = blockIdx.y;
    const int b = bh >> 3, h = bh & 7;
    const int qbase = qt * 128;
    const float scale = 0.1767766952966369f;  // 32^-0.5

    const int r_lo = qbase + warp * 16 + g;
    const int r_hi = r_lo + 8;
    const int rl_c = min(r_lo, NSEQ - 1), rh_c = min(r_hi, NSEQ - 1);

    uint32_t aq[2][4];
    {
        const float* qlo = &g_qkv[((size_t)b * NSEQ + rl_c) * 768 + h * 32];
        const float* qhi = &g_qkv[((size_t)b * NSEQ + rh_c) * 768 + h * 32];
        #pragma unroll
        for (int kk = 0; kk < 2; kk++) {
            float2 x0 = *(const float2*)(qlo + kk * 16 + 2 * t);
            float2 x1 = *(const float2*)(qhi + kk * 16 + 2 * t);
            float2 x2 = *(const float2*)(qlo + kk * 16 + 2 * t + 8);
            float2 x3 = *(const float2*)(qhi + kk * 16 + 2 * t + 8);
            aq[kk][0] = pack_bf16(x0.x, x0.y);
            aq[kk][1] = pack_bf16(x1.x, x1.y);
            aq[kk][2] = pack_bf16(x2.x, x2.y);
            aq[kk][3] = pack_bf16(x3.x, x3.y);
        }
    }

    float accO[4][4];
    #pragma unroll
    for (int i = 0; i < 4; i++)
        #pragma unroll
        for (int j = 0; j < 4; j++) accO[i][j] = 0.f;
    float m_lo = -1e30f, m_hi = -1e30f, l_lo = 0.f, l_hi = 0.f;

    for (int kt = 0; kt < 10; kt++) {
        const int kb = kt * 128;
        __syncthreads();
        // --- stage K (row-major) and V (transposed) tiles, bf16 ---
        {
            int kl0 = tid >> 3;
            int d0  = (tid & 7) * 4;
            #pragma unroll
            for (int it = 0; it < 4; it++) {
                int kl  = kl0 + it * 32;
                int key = kb + kl;
                float4 kv = make_float4(0.f, 0.f, 0.f, 0.f);
                float4 vv = make_float4(0.f, 0.f, 0.f, 0.f);
                if (key < NSEQ) {
                    const float* base = &g_qkv[((size_t)b * NSEQ + key) * 768 + h * 32 + d0];
                    kv = *(const float4*)(base + 256);
                    vv = *(const float4*)(base + 512);
                }
                __nv_bfloat162* kd = (__nv_bfloat162*)&Ks[kl * 36 + d0];
                kd[0] = __floats2bfloat162_rn(kv.x, kv.y);
                kd[1] = __floats2bfloat162_rn(kv.z, kv.w);
                Vt[(d0 + 0) * 136 + kl] = __float2bfloat16(vv.x);
                Vt[(d0 + 1) * 136 + kl] = __float2bfloat16(vv.y);
                Vt[(d0 + 2) * 136 + kl] = __float2bfloat16(vv.z);
                Vt[(d0 + 3) * 136 + kl] = __float2bfloat16(vv.w);
            }
        }
        // --- stage bias tile ---
        {
            int rr = tid >> 1;
            int cb = (tid & 1) * 64;
            int ie = min(qbase + rr, NSEQ - 1);
            const uint4* src = (const uint4*)&g_bias[((size_t)h * NSEQ + ie) * NPAD + kb + cb];
            uint4* dst = (uint4*)((char*)Bias + rr * 272 + cb * 2);
            #pragma unroll
            for (int u = 0; u < 8; u++) dst[u] = src[u];
        }
        if (tid < 128) {
            int key = kb + tid;
            MAdd[tid] = (key < NSEQ) ? g_madd[b * NSEQ + key] : -3e38f;
        }
        __syncthreads();

        // --- S = Q K^T ---
        float S[16][4];
        #pragma unroll
        for (int nt = 0; nt < 16; nt++) {
            S[nt][0] = S[nt][1] = S[nt][2] = S[nt][3] = 0.f;
            #pragma unroll
            for (int kk = 0; kk < 2; kk++) {
                const char* kr = (const char*)Ks + (nt * 8 + g) * 72 + kk * 32 + 4 * t;
                uint32_t b0 = *(const uint32_t*)kr;
                uint32_t b1 = *(const uint32_t*)(kr + 16);
                mma_bf16(S[nt][0], S[nt][1], S[nt][2], S[nt][3],
                         aq[kk][0], aq[kk][1], aq[kk][2], aq[kk][3], b0, b1);
            }
        }
        // --- logits: scale + bias + mask; row max ---
        float tmax_lo = -3e38f, tmax_hi = -3e38f;
        #pragma unroll
        for (int nt = 0; nt < 16; nt++) {
            const char* bb = (const char*)Bias;
            __nv_bfloat162 blo = *(const __nv_bfloat162*)(bb + (warp * 16 + g    ) * 272 + (nt * 8 + 2 * t) * 2);
            __nv_bfloat162 bhi = *(const __nv_bfloat162*)(bb + (warp * 16 + g + 8) * 272 + (nt * 8 + 2 * t) * 2);
            float ma = MAdd[nt * 8 + 2 * t], mb = MAdd[nt * 8 + 2 * t + 1];
            S[nt][0] = S[nt][0] * scale + __bfloat162float(blo.x) + ma;
            S[nt][1] = S[nt][1] * scale + __bfloat162float(blo.y) + mb;
            S[nt][2] = S[nt][2] * scale + __bfloat162float(bhi.x) + ma;
            S[nt][3] = S[nt][3] * scale + __bfloat162float(bhi.y) + mb;
            tmax_lo = fmaxf(tmax_lo, fmaxf(S[nt][0], S[nt][1]));
            tmax_hi = fmaxf(tmax_hi, fmaxf(S[nt][2], S[nt][3]));
        }
        tmax_lo = fmaxf(tmax_lo, __shfl_xor_sync(0xffffffffu, tmax_lo, 1));
        tmax_lo = fmaxf(tmax_lo, __shfl_xor_sync(0xffffffffu, tmax_lo, 2));
        tmax_hi = fmaxf(tmax_hi, __shfl_xor_sync(0xffffffffu, tmax_hi, 1));
        tmax_hi = fmaxf(tmax_hi, __shfl_xor_sync(0xffffffffu, tmax_hi, 2));
        float mn_lo = fmaxf(m_lo, tmax_lo), mn_hi = fmaxf(m_hi, tmax_hi);
        float al = __expf(m_lo - mn_lo), ah = __expf(m_hi - mn_hi);
        m_lo = mn_lo; m_hi = mn_hi;
        float sl = 0.f, sh = 0.f;
        #pragma unroll
        for (int nt = 0; nt < 16; nt++) {
            S[nt][0] = __expf(S[nt][0] - m_lo);
            S[nt][1] = __expf(S[nt][1] - m_lo);
            S[nt][2] = __expf(S[nt][2] - m_hi);
            S[nt][3] = __expf(S[nt][3] - m_hi);
            sl += S[nt][0] + S[nt][1];
            sh += S[nt][2] + S[nt][3];
        }
        sl += __shfl_xor_sync(0xffffffffu, sl, 1); sl += __shfl_xor_sync(0xffffffffu, sl, 2);
        sh += __shfl_xor_sync(0xffffffffu, sh, 1); sh += __shfl_xor_sync(0xffffffffu, sh, 2);
        l_lo = l_lo * al + sl;
        l_hi = l_hi * ah + sh;
        #pragma unroll
        for (int no = 0; no < 4; no++) {
            accO[no][0] *= al; accO[no][1] *= al;
            accO[no][2] *= ah; accO[no][3] *= ah;
        }
        // --- O += P V (P regs reused as A fragments) ---
        #pragma unroll
        for (int j = 0; j < 8; j++) {
            uint32_t a0 = pack_bf16(S[2 * j][0],     S[2 * j][1]);
            uint32_t a1 = pack_bf16(S[2 * j][2],     S[2 * j][3]);
            uint32_t a2 = pack_bf16(S[2 * j + 1][0], S[2 * j + 1][1]);
            uint32_t a3 = pack_bf16(S[2 * j + 1][2], S[2 * j + 1][3]);
            #pragma unroll
            for (int no = 0; no < 4; no++) {
                const char* vr = (const char*)Vt + (no * 8 + g) * 272 + (16 * j + 2 * t) * 2;
                uint32_t b0 = *(const uint32_t*)vr;
                uint32_t b1 = *(const uint32_t*)(vr + 16);
                mma_bf16(accO[no][0], accO[no][1], accO[no][2], accO[no][3],
                         a0, a1, a2, a3, b0, b1);
            }
        }
    }

    float il = 1.f / l_lo;
    float ih = 1.f / l_hi;
    if (r_lo < NSEQ) {
        #pragma unroll
        for (int no = 0; no < 4; no++) {
            float2 v = make_float2(accO[no][0] * il, accO[no][1] * il);
            *(float2*)&g_att[((size_t)b * NSEQ + r_lo) * 256 + h * 32 + no * 8 + 2 * t] = v;
        }
    }
    if (r_hi < NSEQ) {
        #pragma unroll
        for (int no = 0; no < 4; no++) {
            float2 v = make_float2(accO[no][2] * ih, accO[no][3] * ih);
            *(float2*)&g_att[((size_t)b * NSEQ + r_hi) * 256 + h * 32 + no * 8 + 2 * t] = v;
        }
    }
}

// ---------------- launch ----------------
extern "C" void kernel_launch(void* const* d_in, const int* in_sizes, int n_in,
                              void* d_out, int out_size) {
    const float*         x       = (const float*)d_in[0];
    const unsigned char* mask    = (const unsigned char*)d_in[1];
    const float*         w_qkv   = (const float*)d_in[2];
    const float*         w_proj  = (const float*)d_in[3];
    const float*         b_proj  = (const float*)d_in[4];
    const float*         rpb     = (const float*)d_in[5];
    const int*           relidx  = (const int*)d_in[6];
    const int num_rel = in_sizes[5] / H_;

    const int GEMM_SMEM = 2 * 128 * 68 * 4;           // 69632
    const int ATTN_SMEM = 9216 + 8704 + 34816 + 512;  // 53248
    cudaFuncSetAttribute(gemm_tf32<false>, cudaFuncAttributeMaxDynamicSharedMemorySize, GEMM_SMEM);
    cudaFuncSetAttribute(gemm_tf32<true>,  cudaFuncAttributeMaxDynamicSharedMemorySize, GEMM_SMEM);
    cudaFuncSetAttribute(attn_kernel,      cudaFuncAttributeMaxDynamicSharedMemorySize, ATTN_SMEM);

    void *p_qkv = nullptr, *p_att = nullptr;
    cudaGetSymbolAddress(&p_qkv, g_qkv);
    cudaGetSymbolAddress(&p_att, g_att);

    mask_kernel<<<1, 256>>>(mask);
    bias_kernel<<<(NSEQ * NPAD + 255) / 256, 256>>>(relidx, rpb, num_rel);
    gemm_tf32<false><<<dim3(MROWS / 128, 768 / 128), 256, GEMM_SMEM>>>(
        x, w_qkv, nullptr, (float*)p_qkv, 768);
    attn_kernel<<<dim3(10, B_ * H_), 256, ATTN_SMEM>>>();
    gemm_tf32<true><<<dim3(MROWS / 128, 256 / 128), 256, GEMM_SMEM>>>(
        (const float*)p_att, w_proj, b_proj, (float*)d_out, 256);
}

// round 3
// speedup vs baseline: 1.0030x; 1.0030x over previous
#include <cuda_runtime.h>
#include <cuda_bf16.h>
#include <cstdint>

#define B_    16
#define NSEQ  1168
#define H_    8
#define DH    32
#define C_    256
#define NPAD  1280
#define MROWS (B_*NSEQ)   // 18688 = 146*128

// ---------------- scratch (device globals; no runtime alloc) ----------------
__device__ float          g_qkv[(size_t)MROWS * 768];          // 57.4 MB
__device__ __nv_bfloat16  g_bias[(size_t)H_ * NSEQ * NPAD];    // 23.9 MB
__device__ float          g_att[(size_t)MROWS * C_];           // 19.1 MB
__device__ float          g_madd[(size_t)B_ * NSEQ];           // additive mask

// ---------------- helpers ----------------
__device__ __forceinline__ float tf32r(float x) {
    uint32_t u;
    asm("cvt.rna.tf32.f32 %0, %1;" : "=r"(u) : "f"(x));
    return __uint_as_float(u);
}
__device__ __forceinline__ uint32_t pack_bf16(float x, float y) {
    __nv_bfloat162 h = __floats2bfloat162_rn(x, y);
    return *reinterpret_cast<uint32_t*>(&h);
}
__device__ __forceinline__ void mma_tf32(float& d0, float& d1, float& d2, float& d3,
                                         uint32_t a0, uint32_t a1, uint32_t a2, uint32_t a3,
                                         uint32_t b0, uint32_t b1) {
    asm volatile("mma.sync.aligned.m16n8k8.row.col.f32.tf32.tf32.f32 "
                 "{%0,%1,%2,%3},{%4,%5,%6,%7},{%8,%9},{%0,%1,%2,%3};"
                 : "+f"(d0), "+f"(d1), "+f"(d2), "+f"(d3)
                 : "r"(a0), "r"(a1), "r"(a2), "r"(a3), "r"(b0), "r"(b1));
}
__device__ __forceinline__ void mma_bf16(float& d0, float& d1, float& d2, float& d3,
                                         uint32_t a0, uint32_t a1, uint32_t a2, uint32_t a3,
                                         uint32_t b0, uint32_t b1) {
    asm volatile("mma.sync.aligned.m16n8k16.row.col.f32.bf16.bf16.f32 "
                 "{%0,%1,%2,%3},{%4,%5,%6,%7},{%8,%9},{%0,%1,%2,%3};"
                 : "+f"(d0), "+f"(d1), "+f"(d2), "+f"(d3)
                 : "r"(a0), "r"(a1), "r"(a2), "r"(a3), "r"(b0), "r"(b1));
}

// ---------------- 0) mask canonicalization (dtype auto-detect) ----------------
// The reference mask is a JAX bool; the harness may hand it to us as uint8,
// int32 or float32. Detect by byte-lane occupancy (value-based, deterministic):
//   uint8  : nonzero bytes appear at i%4==1
//   float32: 1.0f = 00 00 80 3F -> nonzero only at i%4 in {2,3}
//   int32  : 1    = 01 00 00 00 -> nonzero only at i%4==0
__global__ void mask_kernel(const unsigned char* __restrict__ mraw) {
    __shared__ int s_pos[4];
    if (threadIdx.x < 4) s_pos[threadIdx.x] = 0;
    __syncthreads();
    int loc[4] = {0, 0, 0, 0};
    for (int i = threadIdx.x; i < 4096; i += blockDim.x)
        if (mraw[i]) loc[i & 3] = 1;
    #pragma unroll
    for (int p = 0; p < 4; p++)
        if (loc[p]) atomicOr(&s_pos[p], 1);
    __syncthreads();
    int mode;                 // 0=uint8, 1=int32, 2=float32
    if (s_pos[1]) mode = 0;
    else if (s_pos[2] | s_pos[3]) mode = 2;
    else mode = 1;
    const int total = B_ * NSEQ;
    for (int i = threadIdx.x; i < total; i += blockDim.x) {
        bool m;
        if (mode == 0)      m = mraw[i] != 0;
        else if (mode == 1) m = ((const int*)mraw)[i] != 0;
        else                m = ((const float*)mraw)[i] != 0.f;
        g_madd[i] = m ? -3e38f : 0.f;
    }
}

// ---------------- 1) relative-position bias gather ----------------
__global__ void bias_kernel(const int* __restrict__ rel_index,
                            const float* __restrict__ rpb, int num_rel) {
    int idx = blockIdx.x * blockDim.x + threadIdx.x;
    if (idx >= NSEQ * NPAD) return;
    int i = idx / NPAD;
    int j = idx - i * NPAD;
    if (j < NSEQ) {
        int r = rel_index[i * NSEQ + j];
        #pragma unroll
        for (int h = 0; h < H_; h++)
            g_bias[((size_t)h * NSEQ + i) * NPAD + j] = __float2bfloat16(rpb[h * num_rel + r]);
    } else {
        #pragma unroll
        for (int h = 0; h < H_; h++)
            g_bias[((size_t)h * NSEQ + i) * NPAD + j] = __float2bfloat16(0.f);
    }
}

// ---------------- 2/4) tf32 GEMM: C[M,Nt] = A[M,256] * W[Nt,256]^T (+bias) ----------------
template<bool ADD_BIAS>
__global__ __launch_bounds__(256)
void gemm_tf32(const float* __restrict__ A, const float* __restrict__ W,
               const float* __restrict__ bias, float* __restrict__ Cout, int Ntotal) {
    extern __shared__ float sm[];
    float* As = sm;               // [128][68]
    float* Bs = sm + 128 * 68;    // [128][68]
    const int tid  = threadIdx.x;
    const int warp = tid >> 5, lane = tid & 31;
    const int g = lane >> 2, t = lane & 3;
    const int wm = warp >> 1, wn = warp & 1;
    const int bm = blockIdx.x, bn = blockIdx.y;

    float acc[2][8][4];
    #pragma unroll
    for (int i = 0; i < 2; i++)
        #pragma unroll
        for (int j = 0; j < 8; j++)
            #pragma unroll
            for (int k = 0; k < 4; k++) acc[i][j][k] = 0.f;

    for (int kc = 0; kc < 4; kc++) {
        {
            int r  = tid >> 4;            // 0..15
            int c4 = (tid & 15) * 4;      // 0..60
            const float* Ag = A + ((size_t)(bm * 128 + r)) * 256 + kc * 64 + c4;
            const float* Bg = W + ((size_t)(bn * 128 + r)) * 256 + kc * 64 + c4;
            #pragma unroll
            for (int it = 0; it < 8; it++) {
                float4 av = *(const float4*)(Ag + (size_t)it * 16 * 256);
                float4 bv = *(const float4*)(Bg + (size_t)it * 16 * 256);
                float* ad = &As[(r + it * 16) * 68 + c4];
                float* bd = &Bs[(r + it * 16) * 68 + c4];
                ad[0] = tf32r(av.x); ad[1] = tf32r(av.y); ad[2] = tf32r(av.z); ad[3] = tf32r(av.w);
                bd[0] = tf32r(bv.x); bd[1] = tf32r(bv.y); bd[2] = tf32r(bv.z); bd[3] = tf32r(bv.w);
            }
        }
        __syncthreads();
        #pragma unroll
        for (int ks = 0; ks < 8; ks++) {
            int k0 = ks * 8;
            uint32_t aF[2][4];
            #pragma unroll
            for (int mt = 0; mt < 2; mt++) {
                int m0 = wm * 32 + mt * 16;
                aF[mt][0] = __float_as_uint(As[(m0 + g    ) * 68 + k0 + t    ]);
                aF[mt][1] = __float_as_uint(As[(m0 + g + 8) * 68 + k0 + t    ]);
                aF[mt][2] = __float_as_uint(As[(m0 + g    ) * 68 + k0 + t + 4]);
                aF[mt][3] = __float_as_uint(As[(m0 + g + 8) * 68 + k0 + t + 4]);
            }
            #pragma unroll
            for (int nt = 0; nt < 8; nt++) {
                int n0 = wn * 64 + nt * 8;
                uint32_t b0 = __float_as_uint(Bs[(n0 + g) * 68 + k0 + t    ]);
                uint32_t b1 = __float_as_uint(Bs[(n0 + g) * 68 + k0 + t + 4]);
                mma_tf32(acc[0][nt][0], acc[0][nt][1], acc[0][nt][2], acc[0][nt][3],
                         aF[0][0], aF[0][1], aF[0][2], aF[0][3], b0, b1);
                mma_tf32(acc[1][nt][0], acc[1][nt][1], acc[1][nt][2], acc[1][nt][3],
                         aF[1][0], aF[1][1], aF[1][2], aF[1][3], b0, b1);
            }
        }
        __syncthreads();
    }
    #pragma unroll
    for (int mt = 0; mt < 2; mt++) {
        int r0 = bm * 128 + wm * 32 + mt * 16 + g;
        #pragma unroll
        for (int nt = 0; nt < 8; nt++) {
            int c0 = bn * 128 + wn * 64 + nt * 8 + 2 * t;
            float bb0 = 0.f, bb1 = 0.f;
            if (ADD_BIAS) { bb0 = bias[c0]; bb1 = bias[c0 + 1]; }
            float2 v0 = make_float2(acc[mt][nt][0] + bb0, acc[mt][nt][1] + bb1);
            float2 v1 = make_float2(acc[mt][nt][2] + bb0, acc[mt][nt][3] + bb1);
            *(float2*)&Cout[(size_t)r0       * Ntotal + c0] = v0;
            *(float2*)&Cout[(size_t)(r0 + 8) * Ntotal + c0] = v1;
        }
    }
}

// ---------------- 3) flash attention (bf16 mma, online softmax) ----------------
__global__ __launch_bounds__(256)
void attn_kernel() {
    extern __shared__ char smx[];
    __nv_bfloat16* Ks   = (__nv_bfloat16*)smx;                      // [128][36]  9216 B
    __nv_bfloat16* Vt   = (__nv_bfloat16*)(smx + 9216);             // [32][136]  8704 B
    __nv_bfloat16* Bias = (__nv_bfloat16*)(smx + 9216 + 8704);      // [128][136] 34816 B
    float*         MAdd = (float*)(smx + 9216 + 8704 + 34816);      // [128]      512 B

    const int tid  = threadIdx.x;
    const int warp = tid >> 5, lane = tid & 31;
    const int g = lane >> 2, t = lane & 3;
    const int qt = blockIdx.x, bh = blockIdx.y;
    const int b = bh >> 3, h = bh & 7;
    const int qbase = qt * 128;
    const float scale = 0.1767766952966369f;  // 32^-0.5

    const int r_lo = qbase + warp * 16 + g;
    const int r_hi = r_lo + 8;
    const int rl_c = min(r_lo, NSEQ - 1), rh_c = min(r_hi, NSEQ - 1);

    uint32_t aq[2][4];
    {
        const float* qlo = &g_qkv[((size_t)b * NSEQ + rl_c) * 768 + h * 32];
        const float* qhi = &g_qkv[((size_t)b * NSEQ + rh_c) * 768 + h * 32];
        #pragma unroll
        for (int kk = 0; kk < 2; kk++) {
            float2 x0 = *(const float2*)(qlo + kk * 16 + 2 * t);
            float2 x1 = *(const float2*)(qhi + kk * 16 + 2 * t);
            float2 x2 = *(const float2*)(qlo + kk * 16 + 2 * t + 8);
            float2 x3 = *(const float2*)(qhi + kk * 16 + 2 * t + 8);
            aq[kk][0] = pack_bf16(x0.x, x0.y);
            aq[kk][1] = pack_bf16(x1.x, x1.y);
            aq[kk][2] = pack_bf16(x2.x, x2.y);
            aq[kk][3] = pack_bf16(x3.x, x3.y);
        }
    }

    float accO[4][4];
    #pragma unroll
    for (int i = 0; i < 4; i++)
        #pragma unroll
        for (int j = 0; j < 4; j++) accO[i][j] = 0.f;
    float m_lo = -1e30f, m_hi = -1e30f, l_lo = 0.f, l_hi = 0.f;

    for (int kt = 0; kt < 10; kt++) {
        const int kb = kt * 128;
        __syncthreads();
        // --- stage K (row-major) and V (transposed) tiles, bf16 ---
        {
            int kl0 = tid >> 3;
            int d0  = (tid & 7) * 4;
            #pragma unroll
            for (int it = 0; it < 4; it++) {
                int kl  = kl0 + it * 32;
                int key = kb + kl;
                float4 kv = make_float4(0.f, 0.f, 0.f, 0.f);
                float4 vv = make_float4(0.f, 0.f, 0.f, 0.f);
                if (key < NSEQ) {
                    const float* base = &g_qkv[((size_t)b * NSEQ + key) * 768 + h * 32 + d0];
                    kv = *(const float4*)(base + 256);
                    vv = *(const float4*)(base + 512);
                }
                __nv_bfloat162* kd = (__nv_bfloat162*)&Ks[kl * 36 + d0];
                kd[0] = __floats2bfloat162_rn(kv.x, kv.y);
                kd[1] = __floats2bfloat162_rn(kv.z, kv.w);
                Vt[(d0 + 0) * 136 + kl] = __float2bfloat16(vv.x);
                Vt[(d0 + 1) * 136 + kl] = __float2bfloat16(vv.y);
                Vt[(d0 + 2) * 136 + kl] = __float2bfloat16(vv.z);
                Vt[(d0 + 3) * 136 + kl] = __float2bfloat16(vv.w);
            }
        }
        // --- stage bias tile ---
        {
            int rr = tid >> 1;
            int cb = (tid & 1) * 64;
            int ie = min(qbase + rr, NSEQ - 1);
            const uint4* src = (const uint4*)&g_bias[((size_t)h * NSEQ + ie) * NPAD + kb + cb];
            uint4* dst = (uint4*)((char*)Bias + rr * 272 + cb * 2);
            #pragma unroll
            for (int u = 0; u < 8; u++) dst[u] = src[u];
        }
        if (tid < 128) {
            int key = kb + tid;
            MAdd[tid] = (key < NSEQ) ? g_madd[b * NSEQ + key] : -3e38f;
        }
        __syncthreads();

        // --- S = Q K^T ---
        float S[16][4];
        #pragma unroll
        for (int nt = 0; nt < 16; nt++) {
            S[nt][0] = S[nt][1] = S[nt][2] = S[nt][3] = 0.f;
            #pragma unroll
            for (int kk = 0; kk < 2; kk++) {
                const char* kr = (const char*)Ks + (nt * 8 + g) * 72 + kk * 32 + 4 * t;
                uint32_t b0 = *(const uint32_t*)kr;
                uint32_t b1 = *(const uint32_t*)(kr + 16);
                mma_bf16(S[nt][0], S[nt][1], S[nt][2], S[nt][3],
                         aq[kk][0], aq[kk][1], aq[kk][2], aq[kk][3], b0, b1);
            }
        }
        // --- logits: scale + bias + mask; row max ---
        float tmax_lo = -3e38f, tmax_hi = -3e38f;
        #pragma unroll
        for (int nt = 0; nt < 16; nt++) {
            const char* bb = (const char*)Bias;
            __nv_bfloat162 blo = *(const __nv_bfloat162*)(bb + (warp * 16 + g    ) * 272 + (nt * 8 + 2 * t) * 2);
            __nv_bfloat162 bhi = *(const __nv_bfloat162*)(bb + (warp * 16 + g + 8) * 272 + (nt * 8 + 2 * t) * 2);
            float ma = MAdd[nt * 8 + 2 * t], mb = MAdd[nt * 8 + 2 * t + 1];
            S[nt][0] = S[nt][0] * scale + __bfloat162float(blo.x) + ma;
            S[nt][1] = S[nt][1] * scale + __bfloat162float(blo.y) + mb;
            S[nt][2] = S[nt][2] * scale + __bfloat162float(bhi.x) + ma;
            S[nt][3] = S[nt][3] * scale + __bfloat162float(bhi.y) + mb;
            tmax_lo = fmaxf(tmax_lo, fmaxf(S[nt][0], S[nt][1]));
            tmax_hi = fmaxf(tmax_hi, fmaxf(S[nt][2], S[nt][3]));
        }
        tmax_lo = fmaxf(tmax_lo, __shfl_xor_sync(0xffffffffu, tmax_lo, 1));
        tmax_lo = fmaxf(tmax_lo, __shfl_xor_sync(0xffffffffu, tmax_lo, 2));
        tmax_hi = fmaxf(tmax_hi, __shfl_xor_sync(0xffffffffu, tmax_hi, 1));
        tmax_hi = fmaxf(tmax_hi, __shfl_xor_sync(0xffffffffu, tmax_hi, 2));
        float mn_lo = fmaxf(m_lo, tmax_lo), mn_hi = fmaxf(m_hi, tmax_hi);
        float al = __expf(m_lo - mn_lo), ah = __expf(m_hi - mn_hi);
        m_lo = mn_lo; m_hi = mn_hi;
        float sl = 0.f, sh = 0.f;
        #pragma unroll
        for (int nt = 0; nt < 16; nt++) {
            S[nt][0] = __expf(S[nt][0] - m_lo);
            S[nt][1] = __expf(S[nt][1] - m_lo);
            S[nt][2] = __expf(S[nt][2] - m_hi);
            S[nt][3] = __expf(S[nt][3] - m_hi);
            sl += S[nt][0] + S[nt][1];
            sh += S[nt][2] + S[nt][3];
        }
        sl += __shfl_xor_sync(0xffffffffu, sl, 1); sl += __shfl_xor_sync(0xffffffffu, sl, 2);
        sh += __shfl_xor_sync(0xffffffffu, sh, 1); sh += __shfl_xor_sync(0xffffffffu, sh, 2);
        l_lo = l_lo * al + sl;
        l_hi = l_hi * ah + sh;
        #pragma unroll
        for (int no = 0; no < 4; no++) {
            accO[no][0] *= al; accO[no][1] *= al;
            accO[no][2] *= ah; accO[no][3] *= ah;
        }
        // --- O += P V (P regs reused as A fragments) ---
        #pragma unroll
        for (int j = 0; j < 8; j++) {
            uint32_t a0 = pack_bf16(S[2 * j][0],     S[2 * j][1]);
            uint32_t a1 = pack_bf16(S[2 * j][2],     S[2 * j][3]);
            uint32_t a2 = pack_bf16(S[2 * j + 1][0], S[2 * j + 1][1]);
            uint32_t a3 = pack_bf16(S[2 * j + 1][2], S[2 * j + 1][3]);
            #pragma unroll
            for (int no = 0; no < 4; no++) {
                const char* vr = (const char*)Vt + (no * 8 + g) * 272 + (16 * j + 2 * t) * 2;
                uint32_t b0 = *(const uint32_t*)vr;
                uint32_t b1 = *(const uint32_t*)(vr + 16);
                mma_bf16(accO[no][0], accO[no][1], accO[no][2], accO[no][3],
                         a0, a1, a2, a3, b0, b1);
            }
        }
    }

    float il = 1.f / l_lo;
    float ih = 1.f / l_hi;
    if (r_lo < NSEQ) {
        #pragma unroll
        for (int no = 0; no < 4; no++) {
            float2 v = make_float2(accO[no][0] * il, accO[no][1] * il);
            *(float2*)&g_att[((size_t)b * NSEQ + r_lo) * 256 + h * 32 + no * 8 + 2 * t] = v;
        }
    }
    if (r_hi < NSEQ) {
        #pragma unroll
        for (int no = 0; no < 4; no++) {
            float2 v = make_float2(accO[no][2] * ih, accO[no][3] * ih);
            *(float2*)&g_att[((size_t)b * NSEQ + r_hi) * 256 + h * 32 + no * 8 + 2 * t] = v;
        }
    }
}

// ---------------- launch ----------------
extern "C" void kernel_launch(void* const* d_in, const int* in_sizes, int n_in,
                              void* d_out, int out_size) {
    const float*         x       = (const float*)d_in[0];
    const unsigned char* mask    = (const unsigned char*)d_in[1];
    const float*         w_qkv   = (const float*)d_in[2];
    const float*         w_proj  = (const float*)d_in[3];
    const float*         b_proj  = (const float*)d_in[4];
    const float*         rpb     = (const float*)d_in[5];
    const int*           relidx  = (const int*)d_in[6];
    const int num_rel = in_sizes[5] / H_;

    const int GEMM_SMEM = 2 * 128 * 68 * 4;           // 69632
    const int ATTN_SMEM = 9216 + 8704 + 34816 + 512;  // 53248
    cudaFuncSetAttribute(gemm_tf32<false>, cudaFuncAttributeMaxDynamicSharedMemorySize, GEMM_SMEM);
    cudaFuncSetAttribute(gemm_tf32<true>,  cudaFuncAttributeMaxDynamicSharedMemorySize, GEMM_SMEM);
    cudaFuncSetAttribute(attn_kernel,      cudaFuncAttributeMaxDynamicSharedMemorySize, ATTN_SMEM);

    void *p_qkv = nullptr, *p_att = nullptr;
    cudaGetSymbolAddress(&p_qkv, g_qkv);
    cudaGetSymbolAddress(&p_att, g_att);

    mask_kernel<<<1, 256>>>(mask);
    bias_kernel<<<(NSEQ * NPAD + 255) / 256, 256>>>(relidx, rpb, num_rel);
    gemm_tf32<false><<<dim3(MROWS / 128, 768 / 128), 256, GEMM_SMEM>>>(
        x, w_qkv, nullptr, (float*)p_qkv, 768);
    attn_kernel<<<dim3(10, B_ * H_), 256, ATTN_SMEM>>>();
    gemm_tf32<true><<<dim3(MROWS / 128, 256 / 128), 256, GEMM_SMEM>>>(
        (const float*)p_att, w_proj, b_proj, (float*)d_out, 256);
}

// round 4
// speedup vs baseline: 1.2272x; 1.2235x over previous
#include <cuda_runtime.h>
#include <cuda_bf16.h>
#include <cstdint>

#define B_    16
#define NSEQ  1168
#define H_    8
#define DH    32
#define C_    256
#define NPAD  1280
#define MROWS (B_*NSEQ)   // 18688 = 146*128

// ---------------- scratch (device globals; no runtime alloc) ----------------
__device__ float          g_qkv[(size_t)MROWS * 768];          // 57.4 MB
__device__ __nv_bfloat16  g_bias[(size_t)H_ * NSEQ * NPAD];    // 23.9 MB
__device__ float          g_att[(size_t)MROWS * C_];           // 19.1 MB
__device__ float          g_madd[(size_t)B_ * NSEQ];           // additive mask

// ---------------- helpers ----------------
__device__ __forceinline__ float tf32r(float x) {
    uint32_t u;
    asm("cvt.rna.tf32.f32 %0, %1;" : "=r"(u) : "f"(x));
    return __uint_as_float(u);
}
__device__ __forceinline__ uint32_t pack_bf16(float x, float y) {
    __nv_bfloat162 h = __floats2bfloat162_rn(x, y);
    return *reinterpret_cast<uint32_t*>(&h);
}
__device__ __forceinline__ float2 unpack_bf16(uint32_t u) {
    __nv_bfloat162 h = *reinterpret_cast<__nv_bfloat162*>(&u);
    return __bfloat1622float2(h);
}
__device__ __forceinline__ void mma_tf32(float& d0, float& d1, float& d2, float& d3,
                                         uint32_t a0, uint32_t a1, uint32_t a2, uint32_t a3,
                                         uint32_t b0, uint32_t b1) {
    asm volatile("mma.sync.aligned.m16n8k8.row.col.f32.tf32.tf32.f32 "
                 "{%0,%1,%2,%3},{%4,%5,%6,%7},{%8,%9},{%0,%1,%2,%3};"
                 : "+f"(d0), "+f"(d1), "+f"(d2), "+f"(d3)
                 : "r"(a0), "r"(a1), "r"(a2), "r"(a3), "r"(b0), "r"(b1));
}
__device__ __forceinline__ void mma_bf16(float& d0, float& d1, float& d2, float& d3,
                                         uint32_t a0, uint32_t a1, uint32_t a2, uint32_t a3,
                                         uint32_t b0, uint32_t b1) {
    asm volatile("mma.sync.aligned.m16n8k16.row.col.f32.bf16.bf16.f32 "
                 "{%0,%1,%2,%3},{%4,%5,%6,%7},{%8,%9},{%0,%1,%2,%3};"
                 : "+f"(d0), "+f"(d1), "+f"(d2), "+f"(d3)
                 : "r"(a0), "r"(a1), "r"(a2), "r"(a3), "r"(b0), "r"(b1));
}
__device__ __forceinline__ void ldsm_x4(uint32_t& r0, uint32_t& r1, uint32_t& r2, uint32_t& r3,
                                        uint32_t addr) {
    asm volatile("ldmatrix.sync.aligned.m8n8.x4.shared.b16 {%0,%1,%2,%3}, [%4];"
                 : "=r"(r0), "=r"(r1), "=r"(r2), "=r"(r3) : "r"(addr));
}
__device__ __forceinline__ void ldsm_x4t(uint32_t& r0, uint32_t& r1, uint32_t& r2, uint32_t& r3,
                                         uint32_t addr) {
    asm volatile("ldmatrix.sync.aligned.m8n8.x4.trans.shared.b16 {%0,%1,%2,%3}, [%4];"
                 : "=r"(r0), "=r"(r1), "=r"(r2), "=r"(r3) : "r"(addr));
}

// ---------------- 0) mask canonicalization (dtype auto-detect) ----------------
__global__ void mask_kernel(const unsigned char* __restrict__ mraw) {
    __shared__ int s_pos[4];
    if (threadIdx.x < 4) s_pos[threadIdx.x] = 0;
    __syncthreads();
    int loc[4] = {0, 0, 0, 0};
    for (int i = threadIdx.x; i < 4096; i += blockDim.x)
        if (mraw[i]) loc[i & 3] = 1;
    #pragma unroll
    for (int p = 0; p < 4; p++)
        if (loc[p]) atomicOr(&s_pos[p], 1);
    __syncthreads();
    int mode;                 // 0=uint8, 1=int32, 2=float32
    if (s_pos[1]) mode = 0;
    else if (s_pos[2] | s_pos[3]) mode = 2;
    else mode = 1;
    const int total = B_ * NSEQ;
    for (int i = threadIdx.x; i < total; i += blockDim.x) {
        bool m;
        if (mode == 0)      m = mraw[i] != 0;
        else if (mode == 1) m = ((const int*)mraw)[i] != 0;
        else                m = ((const float*)mraw)[i] != 0.f;
        g_madd[i] = m ? -3e38f : 0.f;
    }
}

// ---------------- 1) relative-position bias gather ----------------
__global__ void bias_kernel(const int* __restrict__ rel_index,
                            const float* __restrict__ rpb, int num_rel) {
    int idx = blockIdx.x * blockDim.x + threadIdx.x;
    if (idx >= NSEQ * NPAD) return;
    int i = idx / NPAD;
    int j = idx - i * NPAD;
    if (j < NSEQ) {
        int r = rel_index[i * NSEQ + j];
        #pragma unroll
        for (int h = 0; h < H_; h++)
            g_bias[((size_t)h * NSEQ + i) * NPAD + j] = __float2bfloat16(rpb[h * num_rel + r]);
    } else {
        #pragma unroll
        for (int h = 0; h < H_; h++)
            g_bias[((size_t)h * NSEQ + i) * NPAD + j] = __float2bfloat16(0.f);
    }
}

// ---------------- 2/4) tf32 GEMM: C[M,Nt] = A[M,256] * W[Nt,256]^T (+bias) ----------------
template<bool ADD_BIAS>
__global__ __launch_bounds__(256)
void gemm_tf32(const float* __restrict__ A, const float* __restrict__ W,
               const float* __restrict__ bias, float* __restrict__ Cout, int Ntotal) {
    extern __shared__ float sm[];
    float* As = sm;               // [128][68]
    float* Bs = sm + 128 * 68;    // [128][68]
    const int tid  = threadIdx.x;
    const int warp = tid >> 5, lane = tid & 31;
    const int g = lane >> 2, t = lane & 3;
    const int wm = warp >> 1, wn = warp & 1;
    const int bm = blockIdx.x, bn = blockIdx.y;

    float acc[2][8][4];
    #pragma unroll
    for (int i = 0; i < 2; i++)
        #pragma unroll
        for (int j = 0; j < 8; j++)
            #pragma unroll
            for (int k = 0; k < 4; k++) acc[i][j][k] = 0.f;

    for (int kc = 0; kc < 4; kc++) {
        {
            int r  = tid >> 4;            // 0..15
            int c4 = (tid & 15) * 4;      // 0..60
            const float* Ag = A + ((size_t)(bm * 128 + r)) * 256 + kc * 64 + c4;
            const float* Bg = W + ((size_t)(bn * 128 + r)) * 256 + kc * 64 + c4;
            #pragma unroll
            for (int it = 0; it < 8; it++) {
                float4 av = *(const float4*)(Ag + (size_t)it * 16 * 256);
                float4 bv = *(const float4*)(Bg + (size_t)it * 16 * 256);
                float* ad = &As[(r + it * 16) * 68 + c4];
                float* bd = &Bs[(r + it * 16) * 68 + c4];
                ad[0] = tf32r(av.x); ad[1] = tf32r(av.y); ad[2] = tf32r(av.z); ad[3] = tf32r(av.w);
                bd[0] = tf32r(bv.x); bd[1] = tf32r(bv.y); bd[2] = tf32r(bv.z); bd[3] = tf32r(bv.w);
            }
        }
        __syncthreads();
        #pragma unroll
        for (int ks = 0; ks < 8; ks++) {
            int k0 = ks * 8;
            uint32_t aF[2][4];
            #pragma unroll
            for (int mt = 0; mt < 2; mt++) {
                int m0 = wm * 32 + mt * 16;
                aF[mt][0] = __float_as_uint(As[(m0 + g    ) * 68 + k0 + t    ]);
                aF[mt][1] = __float_as_uint(As[(m0 + g + 8) * 68 + k0 + t    ]);
                aF[mt][2] = __float_as_uint(As[(m0 + g    ) * 68 + k0 + t + 4]);
                aF[mt][3] = __float_as_uint(As[(m0 + g + 8) * 68 + k0 + t + 4]);
            }
            #pragma unroll
            for (int nt = 0; nt < 8; nt++) {
                int n0 = wn * 64 + nt * 8;
                uint32_t b0 = __float_as_uint(Bs[(n0 + g) * 68 + k0 + t    ]);
                uint32_t b1 = __float_as_uint(Bs[(n0 + g) * 68 + k0 + t + 4]);
                mma_tf32(acc[0][nt][0], acc[0][nt][1], acc[0][nt][2], acc[0][nt][3],
                         aF[0][0], aF[0][1], aF[0][2], aF[0][3], b0, b1);
                mma_tf32(acc[1][nt][0], acc[1][nt][1], acc[1][nt][2], acc[1][nt][3],
                         aF[1][0], aF[1][1], aF[1][2], aF[1][3], b0, b1);
            }
        }
        __syncthreads();
    }
    #pragma unroll
    for (int mt = 0; mt < 2; mt++) {
        int r0 = bm * 128 + wm * 32 + mt * 16 + g;
        #pragma unroll
        for (int nt = 0; nt < 8; nt++) {
            int c0 = bn * 128 + wn * 64 + nt * 8 + 2 * t;
            float bb0 = 0.f, bb1 = 0.f;
            if (ADD_BIAS) { bb0 = bias[c0]; bb1 = bias[c0 + 1]; }
            float2 v0 = make_float2(acc[mt][nt][0] + bb0, acc[mt][nt][1] + bb1);
            float2 v1 = make_float2(acc[mt][nt][2] + bb0, acc[mt][nt][3] + bb1);
            *(float2*)&Cout[(size_t)r0       * Ntotal + c0] = v0;
            *(float2*)&Cout[(size_t)(r0 + 8) * Ntotal + c0] = v1;
        }
    }
}

// ---------------- 3) flash attention (bf16 mma, ldmatrix, online softmax) ----------------
// smem layout: Ks [128 keys][40 bf16 pitch] @0 (10240B)
//              Vs [128 keys][40 bf16 pitch] @10240 (10240B, row-major; .trans at load)
//              Bias [128 rows][136 bf16 pitch] @20480 (34816B)
//              MAdd [128] float @55296 (512B)   -> total 55808B
#define SM_KS   0
#define SM_VS   10240
#define SM_BI   20480
#define SM_MA   55296
#define ATTN_SMEM 55808

__global__ void __launch_bounds__(256, 2) attn_kernel() {
    extern __shared__ char smx[];
    const uint32_t sbase = (uint32_t)__cvta_generic_to_shared(smx);
    float* MAdd = (float*)(smx + SM_MA);

    const int tid  = threadIdx.x;
    const int warp = tid >> 5, lane = tid & 31;
    const int g = lane >> 2, t = lane & 3;
    const int qt = blockIdx.x, bh = blockIdx.y;
    const int b = bh >> 3, h = bh & 7;
    const int qbase = qt * 128;
    const float scale = 0.1767766952966369f;  // 32^-0.5

    const int r_lo = qbase + warp * 16 + g;
    const int r_hi = r_lo + 8;
    const int rl_c = min(r_lo, NSEQ - 1), rh_c = min(r_hi, NSEQ - 1);

    // Q fragments, pre-scaled by 1/sqrt(Dh)
    uint32_t aq[2][4];
    {
        const float* qlo = &g_qkv[((size_t)b * NSEQ + rl_c) * 768 + h * 32];
        const float* qhi = &g_qkv[((size_t)b * NSEQ + rh_c) * 768 + h * 32];
        #pragma unroll
        for (int kk = 0; kk < 2; kk++) {
            float2 x0 = *(const float2*)(qlo + kk * 16 + 2 * t);
            float2 x1 = *(const float2*)(qhi + kk * 16 + 2 * t);
            float2 x2 = *(const float2*)(qlo + kk * 16 + 2 * t + 8);
            float2 x3 = *(const float2*)(qhi + kk * 16 + 2 * t + 8);
            aq[kk][0] = pack_bf16(x0.x * scale, x0.y * scale);
            aq[kk][1] = pack_bf16(x1.x * scale, x1.y * scale);
            aq[kk][2] = pack_bf16(x2.x * scale, x2.y * scale);
            aq[kk][3] = pack_bf16(x3.x * scale, x3.y * scale);
        }
    }

    // per-thread ldmatrix source addresses (lane-dependent parts precomputed)
    const uint32_t lk_row = (lane & 7);
    const uint32_t lk_grp = (lane >> 3);
    const uint32_t addrK  = sbase + SM_KS + lk_row * 80 + lk_grp * 16;               // + nt*8*80
    const uint32_t addrV  = sbase + SM_VS + ((lk_grp & 1) * 8 + lk_row) * 80
                                  + (lk_grp >> 1) * 16;                               // + j*16*80 + nob*16
    const uint32_t addrB  = sbase + SM_BI + (warp * 16 + lk_row + (lk_grp & 1) * 8) * 272
                                  + (lk_grp >> 1) * 16;                               // + nt*16

    float accO[4][4];
    #pragma unroll
    for (int i = 0; i < 4; i++)
        #pragma unroll
        for (int j = 0; j < 4; j++) accO[i][j] = 0.f;
    float m_lo = -1e30f, m_hi = -1e30f, l_lo = 0.f, l_hi = 0.f;

    for (int kt = 0; kt < 10; kt++) {
        const int kb = kt * 128;
        __syncthreads();
        // --- stage K and V (both row-major, bf16, pitch 80B) ---
        {
            int kl0 = tid >> 3;
            int dd  = tid & 7;            // d chunk of 4
            #pragma unroll
            for (int it = 0; it < 4; it++) {
                int kl  = kl0 + it * 32;
                int key = kb + kl;
                float4 kv = make_float4(0.f, 0.f, 0.f, 0.f);
                float4 vv = make_float4(0.f, 0.f, 0.f, 0.f);
                if (key < NSEQ) {
                    const float* base = &g_qkv[((size_t)b * NSEQ + key) * 768 + h * 32 + dd * 4];
                    kv = *(const float4*)(base + 256);
                    vv = *(const float4*)(base + 512);
                }
                *(uint2*)(smx + SM_KS + kl * 80 + dd * 8) =
                    make_uint2(pack_bf16(kv.x, kv.y), pack_bf16(kv.z, kv.w));
                *(uint2*)(smx + SM_VS + kl * 80 + dd * 8) =
                    make_uint2(pack_bf16(vv.x, vv.y), pack_bf16(vv.z, vv.w));
            }
        }
        // --- stage bias tile (bf16, pitch 272B) ---
        {
            int rr = tid >> 1;
            int cb = (tid & 1) * 64;
            int ie = min(qbase + rr, NSEQ - 1);
            const uint4* src = (const uint4*)&g_bias[((size_t)h * NSEQ + ie) * NPAD + kb + cb];
            uint4* dst = (uint4*)(smx + SM_BI + rr * 272 + cb * 2);
            #pragma unroll
            for (int u = 0; u < 8; u++) dst[u] = src[u];
        }
        if (tid < 128) {
            int key = kb + tid;
            MAdd[tid] = (key < NSEQ) ? g_madd[b * NSEQ + key] : -3e38f;
        }
        __syncthreads();

        // --- S = Q K^T (ldmatrix B fragments) ---
        float S[16][4];
        #pragma unroll
        for (int nt = 0; nt < 16; nt++) {
            S[nt][0] = S[nt][1] = S[nt][2] = S[nt][3] = 0.f;
            uint32_t b0, b1, b2, b3;
            ldsm_x4(b0, b1, b2, b3, addrK + nt * (8 * 80));
            mma_bf16(S[nt][0], S[nt][1], S[nt][2], S[nt][3],
                     aq[0][0], aq[0][1], aq[0][2], aq[0][3], b0, b1);
            mma_bf16(S[nt][0], S[nt][1], S[nt][2], S[nt][3],
                     aq[1][0], aq[1][1], aq[1][2], aq[1][3], b2, b3);
        }
        // --- logits: + bias + mask; row max ---
        float tmax_lo = -3e38f, tmax_hi = -3e38f;
        #pragma unroll
        for (int nt = 0; nt < 16; nt += 2) {
            uint32_t c0, c1, c2, c3;
            ldsm_x4(c0, c1, c2, c3, addrB + nt * 16);
            float2 blo0 = unpack_bf16(c0), bhi0 = unpack_bf16(c1);
            float2 blo1 = unpack_bf16(c2), bhi1 = unpack_bf16(c3);
            float2 mm0 = *(float2*)&MAdd[nt * 8 + 2 * t];
            float2 mm1 = *(float2*)&MAdd[(nt + 1) * 8 + 2 * t];
            S[nt][0]     += blo0.x + mm0.x;  S[nt][1]     += blo0.y + mm0.y;
            S[nt][2]     += bhi0.x + mm0.x;  S[nt][3]     += bhi0.y + mm0.y;
            S[nt + 1][0] += blo1.x + mm1.x;  S[nt + 1][1] += blo1.y + mm1.y;
            S[nt + 1][2] += bhi1.x + mm1.x;  S[nt + 1][3] += bhi1.y + mm1.y;
            tmax_lo = fmaxf(tmax_lo, fmaxf(fmaxf(S[nt][0], S[nt][1]),
                                           fmaxf(S[nt + 1][0], S[nt + 1][1])));
            tmax_hi = fmaxf(tmax_hi, fmaxf(fmaxf(S[nt][2], S[nt][3]),
                                           fmaxf(S[nt + 1][2], S[nt + 1][3])));
        }
        tmax_lo = fmaxf(tmax_lo, __shfl_xor_sync(0xffffffffu, tmax_lo, 1));
        tmax_lo = fmaxf(tmax_lo, __shfl_xor_sync(0xffffffffu, tmax_lo, 2));
        tmax_hi = fmaxf(tmax_hi, __shfl_xor_sync(0xffffffffu, tmax_hi, 1));
        tmax_hi = fmaxf(tmax_hi, __shfl_xor_sync(0xffffffffu, tmax_hi, 2));
        float mn_lo = fmaxf(m_lo, tmax_lo), mn_hi = fmaxf(m_hi, tmax_hi);
        float al = __expf(m_lo - mn_lo), ah = __expf(m_hi - mn_hi);
        m_lo = mn_lo; m_hi = mn_hi;
        float sl = 0.f, sh = 0.f;
        #pragma unroll
        for (int nt = 0; nt < 16; nt++) {
            S[nt][0] = __expf(S[nt][0] - m_lo);
            S[nt][1] = __expf(S[nt][1] - m_lo);
            S[nt][2] = __expf(S[nt][2] - m_hi);
            S[nt][3] = __expf(S[nt][3] - m_hi);
            sl += S[nt][0] + S[nt][1];
            sh += S[nt][2] + S[nt][3];
        }
        sl += __shfl_xor_sync(0xffffffffu, sl, 1); sl += __shfl_xor_sync(0xffffffffu, sl, 2);
        sh += __shfl_xor_sync(0xffffffffu, sh, 1); sh += __shfl_xor_sync(0xffffffffu, sh, 2);
        l_lo = l_lo * al + sl;
        l_hi = l_hi * ah + sh;
        #pragma unroll
        for (int no = 0; no < 4; no++) {
            accO[no][0] *= al; accO[no][1] *= al;
            accO[no][2] *= ah; accO[no][3] *= ah;
        }
        // --- O += P V (P regs as A-frags; V via ldmatrix.trans) ---
        #pragma unroll
        for (int j = 0; j < 8; j++) {
            uint32_t a0 = pack_bf16(S[2 * j][0],     S[2 * j][1]);
            uint32_t a1 = pack_bf16(S[2 * j][2],     S[2 * j][3]);
            uint32_t a2 = pack_bf16(S[2 * j + 1][0], S[2 * j + 1][1]);
            uint32_t a3 = pack_bf16(S[2 * j + 1][2], S[2 * j + 1][3]);
            #pragma unroll
            for (int nob = 0; nob < 4; nob += 2) {
                uint32_t v0, v1, v2, v3;
                ldsm_x4t(v0, v1, v2, v3, addrV + j * (16 * 80) + nob * 16);
                mma_bf16(accO[nob][0], accO[nob][1], accO[nob][2], accO[nob][3],
                         a0, a1, a2, a3, v0, v1);
                mma_bf16(accO[nob + 1][0], accO[nob + 1][1], accO[nob + 1][2], accO[nob + 1][3],
                         a0, a1, a2, a3, v2, v3);
            }
        }
    }

    float il = 1.f / l_lo;
    float ih = 1.f / l_hi;
    if (r_lo < NSEQ) {
        #pragma unroll
        for (int no = 0; no < 4; no++) {
            float2 v = make_float2(accO[no][0] * il, accO[no][1] * il);
            *(float2*)&g_att[((size_t)b * NSEQ + r_lo) * 256 + h * 32 + no * 8 + 2 * t] = v;
        }
    }
    if (r_hi < NSEQ) {
        #pragma unroll
        for (int no = 0; no < 4; no++) {
            float2 v = make_float2(accO[no][2] * ih, accO[no][3] * ih);
            *(float2*)&g_att[((size_t)b * NSEQ + r_hi) * 256 + h * 32 + no * 8 + 2 * t] = v;
        }
    }
}

// ---------------- launch ----------------
extern "C" void kernel_launch(void* const* d_in, const int* in_sizes, int n_in,
                              void* d_out, int out_size) {
    const float*         x       = (const float*)d_in[0];
    const unsigned char* mask    = (const unsigned char*)d_in[1];
    const float*         w_qkv   = (const float*)d_in[2];
    const float*         w_proj  = (const float*)d_in[3];
    const float*         b_proj  = (const float*)d_in[4];
    const float*         rpb     = (const float*)d_in[5];
    const int*           relidx  = (const int*)d_in[6];
    const int num_rel = in_sizes[5] / H_;

    const int GEMM_SMEM = 2 * 128 * 68 * 4;           // 69632
    cudaFuncSetAttribute(gemm_tf32<false>, cudaFuncAttributeMaxDynamicSharedMemorySize, GEMM_SMEM);
    cudaFuncSetAttribute(gemm_tf32<true>,  cudaFuncAttributeMaxDynamicSharedMemorySize, GEMM_SMEM);
    cudaFuncSetAttribute(attn_kernel,      cudaFuncAttributeMaxDynamicSharedMemorySize, ATTN_SMEM);

    void *p_qkv = nullptr, *p_att = nullptr;
    cudaGetSymbolAddress(&p_qkv, g_qkv);
    cudaGetSymbolAddress(&p_att, g_att);

    mask_kernel<<<1, 256>>>(mask);
    bias_kernel<<<(NSEQ * NPAD + 255) / 256, 256>>>(relidx, rpb, num_rel);
    gemm_tf32<false><<<dim3(MROWS / 128, 768 / 128), 256, GEMM_SMEM>>>(
        x, w_qkv, nullptr, (float*)p_qkv, 768);
    attn_kernel<<<dim3(10, B_ * H_), 256, ATTN_SMEM>>>();
    gemm_tf32<true><<<dim3(MROWS / 128, 256 / 128), 256, GEMM_SMEM>>>(
        (const float*)p_att, w_proj, b_proj, (float*)d_out, 256);
}

// round 5
// speedup vs baseline: 1.4918x; 1.2156x over previous
#include <cuda_runtime.h>
#include <cuda_bf16.h>
#include <cstdint>

#define B_    16
#define NSEQ  1168
#define H_    8
#define DH    32
#define C_    256
#define NPAD  1280
#define MROWS (B_*NSEQ)   // 18688 = 146*128
#define QK_SCALE 0.1767766952966369f

// ---------------- scratch (device globals; no runtime alloc) ----------------
__device__ __nv_bfloat16  g_q[(size_t)B_ * H_ * NSEQ * DH];    // 9.6 MB, pre-scaled
__device__ __nv_bfloat16  g_k[(size_t)B_ * H_ * NSEQ * DH];
__device__ __nv_bfloat16  g_v[(size_t)B_ * H_ * NSEQ * DH];
__device__ __nv_bfloat16  g_bias[(size_t)H_ * NSEQ * NPAD];    // 23.9 MB
__device__ float          g_att[(size_t)MROWS * C_];           // 19.1 MB
__device__ float          g_madd[(size_t)B_ * NSEQ];           // additive mask

// ---------------- helpers ----------------
__device__ __forceinline__ float tf32r(float x) {
    uint32_t u;
    asm("cvt.rna.tf32.f32 %0, %1;" : "=r"(u) : "f"(x));
    return __uint_as_float(u);
}
__device__ __forceinline__ uint32_t pack_bf16(float x, float y) {
    __nv_bfloat162 h = __floats2bfloat162_rn(x, y);
    return *reinterpret_cast<uint32_t*>(&h);
}
__device__ __forceinline__ float2 unpack_bf16(uint32_t u) {
    __nv_bfloat162 h = *reinterpret_cast<__nv_bfloat162*>(&u);
    return __bfloat1622float2(h);
}
__device__ __forceinline__ void mma_tf32(float& d0, float& d1, float& d2, float& d3,
                                         uint32_t a0, uint32_t a1, uint32_t a2, uint32_t a3,
                                         uint32_t b0, uint32_t b1) {
    asm volatile("mma.sync.aligned.m16n8k8.row.col.f32.tf32.tf32.f32 "
                 "{%0,%1,%2,%3},{%4,%5,%6,%7},{%8,%9},{%0,%1,%2,%3};"
                 : "+f"(d0), "+f"(d1), "+f"(d2), "+f"(d3)
                 : "r"(a0), "r"(a1), "r"(a2), "r"(a3), "r"(b0), "r"(b1));
}
__device__ __forceinline__ void mma_bf16(float& d0, float& d1, float& d2, float& d3,
                                         uint32_t a0, uint32_t a1, uint32_t a2, uint32_t a3,
                                         uint32_t b0, uint32_t b1) {
    asm volatile("mma.sync.aligned.m16n8k16.row.col.f32.bf16.bf16.f32 "
                 "{%0,%1,%2,%3},{%4,%5,%6,%7},{%8,%9},{%0,%1,%2,%3};"
                 : "+f"(d0), "+f"(d1), "+f"(d2), "+f"(d3)
                 : "r"(a0), "r"(a1), "r"(a2), "r"(a3), "r"(b0), "r"(b1));
}
__device__ __forceinline__ void ldsm_x4(uint32_t& r0, uint32_t& r1, uint32_t& r2, uint32_t& r3,
                                        uint32_t addr) {
    asm volatile("ldmatrix.sync.aligned.m8n8.x4.shared.b16 {%0,%1,%2,%3}, [%4];"
                 : "=r"(r0), "=r"(r1), "=r"(r2), "=r"(r3) : "r"(addr));
}
__device__ __forceinline__ void ldsm_x4t(uint32_t& r0, uint32_t& r1, uint32_t& r2, uint32_t& r3,
                                         uint32_t addr) {
    asm volatile("ldmatrix.sync.aligned.m8n8.x4.trans.shared.b16 {%0,%1,%2,%3}, [%4];"
                 : "=r"(r0), "=r"(r1), "=r"(r2), "=r"(r3) : "r"(addr));
}
__device__ __forceinline__ void cp_async16(uint32_t saddr, const void* gaddr, int srcsize) {
    asm volatile("cp.async.ca.shared.global [%0], [%1], 16, %2;"
                 :: "r"(saddr), "l"(gaddr), "r"(srcsize) : "memory");
}
__device__ __forceinline__ void cp_commit() {
    asm volatile("cp.async.commit_group;" ::: "memory");
}
template<int N> __device__ __forceinline__ void cp_wait() {
    asm volatile("cp.async.wait_group %0;" :: "n"(N) : "memory");
}

// ---------------- 0) mask canonicalization (dtype auto-detect) ----------------
__global__ void mask_kernel(const unsigned char* __restrict__ mraw) {
    __shared__ int s_pos[4];
    if (threadIdx.x < 4) s_pos[threadIdx.x] = 0;
    __syncthreads();
    int loc[4] = {0, 0, 0, 0};
    for (int i = threadIdx.x; i < 4096; i += blockDim.x)
        if (mraw[i]) loc[i & 3] = 1;
    #pragma unroll
    for (int p = 0; p < 4; p++)
        if (loc[p]) atomicOr(&s_pos[p], 1);
    __syncthreads();
    int mode;                 // 0=uint8, 1=int32, 2=float32
    if (s_pos[1]) mode = 0;
    else if (s_pos[2] | s_pos[3]) mode = 2;
    else mode = 1;
    const int total = B_ * NSEQ;
    for (int i = threadIdx.x; i < total; i += blockDim.x) {
        bool m;
        if (mode == 0)      m = mraw[i] != 0;
        else if (mode == 1) m = ((const int*)mraw)[i] != 0;
        else                m = ((const float*)mraw)[i] != 0.f;
        g_madd[i] = m ? -3e38f : 0.f;
    }
}

// ---------------- 1) relative-position bias gather ----------------
__global__ void bias_kernel(const int* __restrict__ rel_index,
                            const float* __restrict__ rpb, int num_rel) {
    int idx = blockIdx.x * blockDim.x + threadIdx.x;
    if (idx >= NSEQ * NPAD) return;
    int i = idx / NPAD;
    int j = idx - i * NPAD;
    if (j < NSEQ) {
        int r = rel_index[i * NSEQ + j];
        #pragma unroll
        for (int h = 0; h < H_; h++)
            g_bias[((size_t)h * NSEQ + i) * NPAD + j] = __float2bfloat16(rpb[h * num_rel + r]);
    } else {
        #pragma unroll
        for (int h = 0; h < H_; h++)
            g_bias[((size_t)h * NSEQ + i) * NPAD + j] = __float2bfloat16(0.f);
    }
}

// ---------------- 2/4) tf32 GEMM: C[M,Nt] = A[M,256] * W[Nt,256]^T ----------------
// MODE 0: QKV — write bf16 q (pre-scaled), k, v in [b][h][n][32] layout.
// MODE 1: proj — write f32 + bias to Cout.
template<int MODE>
__global__ __launch_bounds__(256)
void gemm_tf32(const float* __restrict__ A, const float* __restrict__ W,
               const float* __restrict__ bias, float* __restrict__ Cout, int Ntotal) {
    extern __shared__ float sm[];
    float* As = sm;               // [128][68]
    float* Bs = sm + 128 * 68;    // [128][68]
    const int tid  = threadIdx.x;
    const int warp = tid >> 5, lane = tid & 31;
    const int g = lane >> 2, t = lane & 3;
    const int wm = warp >> 1, wn = warp & 1;
    const int bm = blockIdx.x, bn = blockIdx.y;

    float acc[2][8][4];
    #pragma unroll
    for (int i = 0; i < 2; i++)
        #pragma unroll
        for (int j = 0; j < 8; j++)
            #pragma unroll
            for (int k = 0; k < 4; k++) acc[i][j][k] = 0.f;

    for (int kc = 0; kc < 4; kc++) {
        {
            int r  = tid >> 4;            // 0..15
            int c4 = (tid & 15) * 4;      // 0..60
            const float* Ag = A + ((size_t)(bm * 128 + r)) * 256 + kc * 64 + c4;
            const float* Bg = W + ((size_t)(bn * 128 + r)) * 256 + kc * 64 + c4;
            #pragma unroll
            for (int it = 0; it < 8; it++) {
                float4 av = *(const float4*)(Ag + (size_t)it * 16 * 256);
                float4 bv = *(const float4*)(Bg + (size_t)it * 16 * 256);
                float* ad = &As[(r + it * 16) * 68 + c4];
                float* bd = &Bs[(r + it * 16) * 68 + c4];
                ad[0] = tf32r(av.x); ad[1] = tf32r(av.y); ad[2] = tf32r(av.z); ad[3] = tf32r(av.w);
                bd[0] = tf32r(bv.x); bd[1] = tf32r(bv.y); bd[2] = tf32r(bv.z); bd[3] = tf32r(bv.w);
            }
        }
        __syncthreads();
        #pragma unroll
        for (int ks = 0; ks < 8; ks++) {
            int k0 = ks * 8;
            uint32_t aF[2][4];
            #pragma unroll
            for (int mt = 0; mt < 2; mt++) {
                int m0 = wm * 32 + mt * 16;
                aF[mt][0] = __float_as_uint(As[(m0 + g    ) * 68 + k0 + t    ]);
                aF[mt][1] = __float_as_uint(As[(m0 + g + 8) * 68 + k0 + t    ]);
                aF[mt][2] = __float_as_uint(As[(m0 + g    ) * 68 + k0 + t + 4]);
                aF[mt][3] = __float_as_uint(As[(m0 + g + 8) * 68 + k0 + t + 4]);
            }
            #pragma unroll
            for (int nt = 0; nt < 8; nt++) {
                int n0 = wn * 64 + nt * 8;
                uint32_t b0 = __float_as_uint(Bs[(n0 + g) * 68 + k0 + t    ]);
                uint32_t b1 = __float_as_uint(Bs[(n0 + g) * 68 + k0 + t + 4]);
                mma_tf32(acc[0][nt][0], acc[0][nt][1], acc[0][nt][2], acc[0][nt][3],
                         aF[0][0], aF[0][1], aF[0][2], aF[0][3], b0, b1);
                mma_tf32(acc[1][nt][0], acc[1][nt][1], acc[1][nt][2], acc[1][nt][3],
                         aF[1][0], aF[1][1], aF[1][2], aF[1][3], b0, b1);
            }
        }
        __syncthreads();
    }

    if (MODE == 0) {
        // which tensor this block writes (cols 256-aligned per 'which'; 128-wide block)
        const int which = bn >> 1;
        __nv_bfloat16* dst = (which == 0) ? g_q : (which == 1) ? g_k : g_v;
        const float sc = (which == 0) ? QK_SCALE : 1.f;
        #pragma unroll
        for (int mt = 0; mt < 2; mt++) {
            int r0 = bm * 128 + wm * 32 + mt * 16 + g;
            int r8 = r0 + 8;
            int b0i = r0 / NSEQ, n0 = r0 - b0i * NSEQ;
            int b8i = r8 / NSEQ, n8 = r8 - b8i * NSEQ;
            #pragma unroll
            for (int nt = 0; nt < 8; nt++) {
                int c0 = bn * 128 + wn * 64 + nt * 8 + 2 * t;
                int h = (c0 >> 5) & 7, d = c0 & 31;
                uint32_t lo = pack_bf16(acc[mt][nt][0] * sc, acc[mt][nt][1] * sc);
                uint32_t hi = pack_bf16(acc[mt][nt][2] * sc, acc[mt][nt][3] * sc);
                *(uint32_t*)&dst[((size_t)(b0i * 8 + h) * NSEQ + n0) * 32 + d] = lo;
                *(uint32_t*)&dst[((size_t)(b8i * 8 + h) * NSEQ + n8) * 32 + d] = hi;
            }
        }
    } else {
        #pragma unroll
        for (int mt = 0; mt < 2; mt++) {
            int r0 = bm * 128 + wm * 32 + mt * 16 + g;
            #pragma unroll
            for (int nt = 0; nt < 8; nt++) {
                int c0 = bn * 128 + wn * 64 + nt * 8 + 2 * t;
                float bb0 = bias[c0], bb1 = bias[c0 + 1];
                float2 v0 = make_float2(acc[mt][nt][0] + bb0, acc[mt][nt][1] + bb1);
                float2 v1 = make_float2(acc[mt][nt][2] + bb0, acc[mt][nt][3] + bb1);
                *(float2*)&Cout[(size_t)r0       * Ntotal + c0] = v0;
                *(float2*)&Cout[(size_t)(r0 + 8) * Ntotal + c0] = v1;
            }
        }
    }
}

// ---------------- 3) flash attention (bf16 mma, ldmatrix, cp.async x2 buffers) ----------------
// smem: Kbuf[p] @ p*20480, Vbuf[p] @ p*20480+10240 (pitch 80B, 128 rows x 64B data)
//       MAdd @ 40960 (512B)   -> total 41472B
#define KV_PITCH 80
#define SM_STAGE 20480
#define SM_MA    40960
#define ATTN_SMEM 41472

__global__ void __launch_bounds__(256, 2) attn_kernel() {
    extern __shared__ char smx[];
    const uint32_t sbase = (uint32_t)__cvta_generic_to_shared(smx);
    float* MAdd = (float*)(smx + SM_MA);

    const int tid  = threadIdx.x;
    const int warp = tid >> 5, lane = tid & 31;
    const int g = lane >> 2, t = lane & 3;
    const int qt = blockIdx.x, bh = blockIdx.y;
    const int b = bh >> 3, h = bh & 7;
    const int qbase = qt * 128;

    const int r_lo = qbase + warp * 16 + g;
    const int r_hi = r_lo + 8;
    const int rl_c = min(r_lo, NSEQ - 1), rh_c = min(r_hi, NSEQ - 1);

    const __nv_bfloat16* kbase = g_k + (size_t)bh * NSEQ * 32;
    const __nv_bfloat16* vbase = g_v + (size_t)bh * NSEQ * 32;

    // Q fragments (pre-scaled bf16, direct load)
    uint32_t aq[2][4];
    {
        const __nv_bfloat16* qlo = g_q + ((size_t)bh * NSEQ + rl_c) * 32;
        const __nv_bfloat16* qhi = g_q + ((size_t)bh * NSEQ + rh_c) * 32;
        #pragma unroll
        for (int kk = 0; kk < 2; kk++) {
            aq[kk][0] = *(const uint32_t*)(qlo + kk * 16 + 2 * t);
            aq[kk][1] = *(const uint32_t*)(qhi + kk * 16 + 2 * t);
            aq[kk][2] = *(const uint32_t*)(qlo + kk * 16 + 2 * t + 8);
            aq[kk][3] = *(const uint32_t*)(qhi + kk * 16 + 2 * t + 8);
        }
    }

    // bias fragment base pointers (direct-from-global loads)
    const __nv_bfloat16* blo = g_bias + ((size_t)h * NSEQ + rl_c) * NPAD + 2 * t;
    const __nv_bfloat16* bhi = g_bias + ((size_t)h * NSEQ + rh_c) * NPAD + 2 * t;

    // ldmatrix lane addressing
    const uint32_t lk_row = (lane & 7);
    const uint32_t lk_grp = (lane >> 3);
    const uint32_t offK = lk_row * KV_PITCH + lk_grp * 16;
    const uint32_t offV = ((lk_grp & 1) * 8 + lk_row) * KV_PITCH + (lk_grp >> 1) * 16 + 10240;

    float accO[4][4];
    #pragma unroll
    for (int i = 0; i < 4; i++)
        #pragma unroll
        for (int j = 0; j < 4; j++) accO[i][j] = 0.f;
    float m_lo = -1e30f, m_hi = -1e30f, l_lo = 0.f, l_hi = 0.f;

    // stage tile kt into buffer p via cp.async (one commit group per call)
    auto stage = [&](int kt, int p) {
        const int kb = kt * 128;
        #pragma unroll
        for (int it = 0; it < 2; it++) {
            int idx = tid + it * 256;          // 0..511
            int row = idx >> 2, ch = idx & 3;  // 128 rows x 4 chunks of 16B
            int key = kb + row;
            int sz = (key < NSEQ) ? 16 : 0;
            uint32_t s0 = sbase + p * SM_STAGE + row * KV_PITCH + ch * 16;
            cp_async16(s0,         kbase + (size_t)key * 32 + ch * 8, sz);
            cp_async16(s0 + 10240, vbase + (size_t)key * 32 + ch * 8, sz);
        }
        cp_commit();
    };

    stage(0, 0);

    for (int kt = 0; kt < 10; kt++) {
        const int p  = kt & 1;
        const int kb = kt * 128;
        if (kt < 9) stage(kt + 1, p ^ 1);
        if (tid < 128) {
            int key = kb + tid;
            MAdd[tid] = (key < NSEQ) ? g_madd[b * NSEQ + key] : -3e38f;
        }
        if (kt < 9) cp_wait<1>(); else cp_wait<0>();
        __syncthreads();

        const uint32_t addrK = sbase + p * SM_STAGE + offK;
        const uint32_t addrV = sbase + p * SM_STAGE + offV;

        // --- S = Q K^T ---
        float S[16][4];
        #pragma unroll
        for (int nt = 0; nt < 16; nt++) {
            S[nt][0] = S[nt][1] = S[nt][2] = S[nt][3] = 0.f;
            uint32_t b0, b1, b2, b3;
            ldsm_x4(b0, b1, b2, b3, addrK + nt * (8 * KV_PITCH));
            mma_bf16(S[nt][0], S[nt][1], S[nt][2], S[nt][3],
                     aq[0][0], aq[0][1], aq[0][2], aq[0][3], b0, b1);
            mma_bf16(S[nt][0], S[nt][1], S[nt][2], S[nt][3],
                     aq[1][0], aq[1][1], aq[1][2], aq[1][3], b2, b3);
        }
        // --- + bias (global) + mask (smem); row max ---
        float tmax_lo = -3e38f, tmax_hi = -3e38f;
        #pragma unroll
        for (int nt = 0; nt < 16; nt++) {
            float2 bl = unpack_bf16(*(const uint32_t*)(blo + kb + nt * 8));
            float2 bh2 = unpack_bf16(*(const uint32_t*)(bhi + kb + nt * 8));
            float2 mm = *(float2*)&MAdd[nt * 8 + 2 * t];
            S[nt][0] += bl.x + mm.x;   S[nt][1] += bl.y + mm.y;
            S[nt][2] += bh2.x + mm.x;  S[nt][3] += bh2.y + mm.y;
            tmax_lo = fmaxf(tmax_lo, fmaxf(S[nt][0], S[nt][1]));
            tmax_hi = fmaxf(tmax_hi, fmaxf(S[nt][2], S[nt][3]));
        }
        tmax_lo = fmaxf(tmax_lo, __shfl_xor_sync(0xffffffffu, tmax_lo, 1));
        tmax_lo = fmaxf(tmax_lo, __shfl_xor_sync(0xffffffffu, tmax_lo, 2));
        tmax_hi = fmaxf(tmax_hi, __shfl_xor_sync(0xffffffffu, tmax_hi, 1));
        tmax_hi = fmaxf(tmax_hi, __shfl_xor_sync(0xffffffffu, tmax_hi, 2));
        float mn_lo = fmaxf(m_lo, tmax_lo), mn_hi = fmaxf(m_hi, tmax_hi);
        float al = __expf(m_lo - mn_lo), ah = __expf(m_hi - mn_hi);
        m_lo = mn_lo; m_hi = mn_hi;
        float sl = 0.f, sh = 0.f;
        #pragma unroll
        for (int nt = 0; nt < 16; nt++) {
            S[nt][0] = __expf(S[nt][0] - m_lo);
            S[nt][1] = __expf(S[nt][1] - m_lo);
            S[nt][2] = __expf(S[nt][2] - m_hi);
            S[nt][3] = __expf(S[nt][3] - m_hi);
            sl += S[nt][0] + S[nt][1];
            sh += S[nt][2] + S[nt][3];
        }
        sl += __shfl_xor_sync(0xffffffffu, sl, 1); sl += __shfl_xor_sync(0xffffffffu, sl, 2);
        sh += __shfl_xor_sync(0xffffffffu, sh, 1); sh += __shfl_xor_sync(0xffffffffu, sh, 2);
        l_lo = l_lo * al + sl;
        l_hi = l_hi * ah + sh;
        #pragma unroll
        for (int no = 0; no < 4; no++) {
            accO[no][0] *= al; accO[no][1] *= al;
            accO[no][2] *= ah; accO[no][3] *= ah;
        }
        // --- O += P V ---
        #pragma unroll
        for (int j = 0; j < 8; j++) {
            uint32_t a0 = pack_bf16(S[2 * j][0],     S[2 * j][1]);
            uint32_t a1 = pack_bf16(S[2 * j][2],     S[2 * j][3]);
            uint32_t a2 = pack_bf16(S[2 * j + 1][0], S[2 * j + 1][1]);
            uint32_t a3 = pack_bf16(S[2 * j + 1][2], S[2 * j + 1][3]);
            #pragma unroll
            for (int nob = 0; nob < 4; nob += 2) {
                uint32_t v0, v1, v2, v3;
                ldsm_x4t(v0, v1, v2, v3, addrV + j * (16 * KV_PITCH) + nob * 16);
                mma_bf16(accO[nob][0], accO[nob][1], accO[nob][2], accO[nob][3],
                         a0, a1, a2, a3, v0, v1);
                mma_bf16(accO[nob + 1][0], accO[nob + 1][1], accO[nob + 1][2], accO[nob + 1][3],
                         a0, a1, a2, a3, v2, v3);
            }
        }
        __syncthreads();
    }

    float il = 1.f / l_lo;
    float ih = 1.f / l_hi;
    if (r_lo < NSEQ) {
        #pragma unroll
        for (int no = 0; no < 4; no++) {
            float2 v = make_float2(accO[no][0] * il, accO[no][1] * il);
            *(float2*)&g_att[((size_t)b * NSEQ + r_lo) * 256 + h * 32 + no * 8 + 2 * t] = v;
        }
    }
    if (r_hi < NSEQ) {
        #pragma unroll
        for (int no = 0; no < 4; no++) {
            float2 v = make_float2(accO[no][2] * ih, accO[no][3] * ih);
            *(float2*)&g_att[((size_t)b * NSEQ + r_hi) * 256 + h * 32 + no * 8 + 2 * t] = v;
        }
    }
}

// ---------------- launch ----------------
extern "C" void kernel_launch(void* const* d_in, const int* in_sizes, int n_in,
                              void* d_out, int out_size) {
    const float*         x       = (const float*)d_in[0];
    const unsigned char* mask    = (const unsigned char*)d_in[1];
    const float*         w_qkv   = (const float*)d_in[2];
    const float*         w_proj  = (const float*)d_in[3];
    const float*         b_proj  = (const float*)d_in[4];
    const float*         rpb     = (const float*)d_in[5];
    const int*           relidx  = (const int*)d_in[6];
    const int num_rel = in_sizes[5] / H_;

    const int GEMM_SMEM = 2 * 128 * 68 * 4;           // 69632
    cudaFuncSetAttribute(gemm_tf32<0>, cudaFuncAttributeMaxDynamicSharedMemorySize, GEMM_SMEM);
    cudaFuncSetAttribute(gemm_tf32<1>, cudaFuncAttributeMaxDynamicSharedMemorySize, GEMM_SMEM);
    cudaFuncSetAttribute(attn_kernel,  cudaFuncAttributeMaxDynamicSharedMemorySize, ATTN_SMEM);

    void* p_att = nullptr;
    cudaGetSymbolAddress(&p_att, g_att);

    mask_kernel<<<1, 256>>>(mask);
    bias_kernel<<<(NSEQ * NPAD + 255) / 256, 256>>>(relidx, rpb, num_rel);
    gemm_tf32<0><<<dim3(MROWS / 128, 768 / 128), 256, GEMM_SMEM>>>(
        x, w_qkv, nullptr, nullptr, 768);
    attn_kernel<<<dim3(10, B_ * H_), 256, ATTN_SMEM>>>();
    gemm_tf32<1><<<dim3(MROWS / 128, 256 / 128), 256, GEMM_SMEM>>>(
        (const float*)p_att, w_proj, b_proj, (float*)d_out, 256);
}

// round 6
// speedup vs baseline: 1.5807x; 1.0596x over previous
#include <cuda_runtime.h>
#include <cuda_bf16.h>
#include <cstdint>

#define B_    16
#define NSEQ  1168
#define H_    8
#define DH    32
#define C_    256
#define NPAD  1280
#define MROWS (B_*NSEQ)   // 18688 = 146*128
#define QK_SCALE 0.1767766952966369f

// ---------------- scratch (device globals; no runtime alloc) ----------------
__device__ __nv_bfloat16  g_q[(size_t)B_ * H_ * NSEQ * DH];    // 9.6 MB, pre-scaled
__device__ __nv_bfloat16  g_k[(size_t)B_ * H_ * NSEQ * DH];
__device__ __nv_bfloat16  g_v[(size_t)B_ * H_ * NSEQ * DH];
__device__ __nv_bfloat16  g_bias[(size_t)H_ * NSEQ * NPAD];    // 23.9 MB
__device__ float          g_att[(size_t)MROWS * C_];           // 19.1 MB
__device__ float          g_madd[(size_t)B_ * NSEQ];           // additive mask

// ---------------- helpers ----------------
__device__ __forceinline__ float tf32r(float x) {
    uint32_t u;
    asm("cvt.rna.tf32.f32 %0, %1;" : "=r"(u) : "f"(x));
    return __uint_as_float(u);
}
__device__ __forceinline__ uint32_t pack_bf16(float x, float y) {
    __nv_bfloat162 h = __floats2bfloat162_rn(x, y);
    return *reinterpret_cast<uint32_t*>(&h);
}
__device__ __forceinline__ float2 unpack_bf16(uint32_t u) {
    __nv_bfloat162 h = *reinterpret_cast<__nv_bfloat162*>(&u);
    return __bfloat1622float2(h);
}
__device__ __forceinline__ void mma_tf32(float& d0, float& d1, float& d2, float& d3,
                                         uint32_t a0, uint32_t a1, uint32_t a2, uint32_t a3,
                                         uint32_t b0, uint32_t b1) {
    asm volatile("mma.sync.aligned.m16n8k8.row.col.f32.tf32.tf32.f32 "
                 "{%0,%1,%2,%3},{%4,%5,%6,%7},{%8,%9},{%0,%1,%2,%3};"
                 : "+f"(d0), "+f"(d1), "+f"(d2), "+f"(d3)
                 : "r"(a0), "r"(a1), "r"(a2), "r"(a3), "r"(b0), "r"(b1));
}
__device__ __forceinline__ void mma_bf16(float& d0, float& d1, float& d2, float& d3,
                                         uint32_t a0, uint32_t a1, uint32_t a2, uint32_t a3,
                                         uint32_t b0, uint32_t b1) {
    asm volatile("mma.sync.aligned.m16n8k16.row.col.f32.bf16.bf16.f32 "
                 "{%0,%1,%2,%3},{%4,%5,%6,%7},{%8,%9},{%0,%1,%2,%3};"
                 : "+f"(d0), "+f"(d1), "+f"(d2), "+f"(d3)
                 : "r"(a0), "r"(a1), "r"(a2), "r"(a3), "r"(b0), "r"(b1));
}
__device__ __forceinline__ void ldsm_x4(uint32_t& r0, uint32_t& r1, uint32_t& r2, uint32_t& r3,
                                        uint32_t addr) {
    asm volatile("ldmatrix.sync.aligned.m8n8.x4.shared.b16 {%0,%1,%2,%3}, [%4];"
                 : "=r"(r0), "=r"(r1), "=r"(r2), "=r"(r3) : "r"(addr));
}
__device__ __forceinline__ void ldsm_x4t(uint32_t& r0, uint32_t& r1, uint32_t& r2, uint32_t& r3,
                                         uint32_t addr) {
    asm volatile("ldmatrix.sync.aligned.m8n8.x4.trans.shared.b16 {%0,%1,%2,%3}, [%4];"
                 : "=r"(r0), "=r"(r1), "=r"(r2), "=r"(r3) : "r"(addr));
}
__device__ __forceinline__ void cp_async16(uint32_t saddr, const void* gaddr, int srcsize) {
    asm volatile("cp.async.ca.shared.global [%0], [%1], 16, %2;"
                 :: "r"(saddr), "l"(gaddr), "r"(srcsize) : "memory");
}
__device__ __forceinline__ void cp_commit() {
    asm volatile("cp.async.commit_group;" ::: "memory");
}
template<int N> __device__ __forceinline__ void cp_wait() {
    asm volatile("cp.async.wait_group %0;" :: "n"(N) : "memory");
}

// ---------------- 0) mask canonicalization (dtype auto-detect) ----------------
__global__ void mask_kernel(const unsigned char* __restrict__ mraw) {
    __shared__ int s_pos[4];
    if (threadIdx.x < 4) s_pos[threadIdx.x] = 0;
    __syncthreads();
    int loc[4] = {0, 0, 0, 0};
    for (int i = threadIdx.x; i < 4096; i += blockDim.x)
        if (mraw[i]) loc[i & 3] = 1;
    #pragma unroll
    for (int p = 0; p < 4; p++)
        if (loc[p]) atomicOr(&s_pos[p], 1);
    __syncthreads();
    int mode;                 // 0=uint8, 1=int32, 2=float32
    if (s_pos[1]) mode = 0;
    else if (s_pos[2] | s_pos[3]) mode = 2;
    else mode = 1;
    const int total = B_ * NSEQ;
    for (int i = threadIdx.x; i < total; i += blockDim.x) {
        bool m;
        if (mode == 0)      m = mraw[i] != 0;
        else if (mode == 1) m = ((const int*)mraw)[i] != 0;
        else                m = ((const float*)mraw)[i] != 0.f;
        g_madd[i] = m ? -3e38f : 0.f;
    }
}

// ---------------- 1) relative-position bias gather ----------------
__global__ void bias_kernel(const int* __restrict__ rel_index,
                            const float* __restrict__ rpb, int num_rel) {
    int idx = blockIdx.x * blockDim.x + threadIdx.x;
    if (idx >= NSEQ * NPAD) return;
    int i = idx / NPAD;
    int j = idx - i * NPAD;
    if (j < NSEQ) {
        int r = rel_index[i * NSEQ + j];
        #pragma unroll
        for (int h = 0; h < H_; h++)
            g_bias[((size_t)h * NSEQ + i) * NPAD + j] = __float2bfloat16(rpb[h * num_rel + r]);
    } else {
        #pragma unroll
        for (int h = 0; h < H_; h++)
            g_bias[((size_t)h * NSEQ + i) * NPAD + j] = __float2bfloat16(0.f);
    }
}

// ---------------- 2/4) tf32 GEMM: C[M,Nt] = A[M,256] * W[Nt,256]^T ----------------
// MODE 0: QKV — write bf16 q (pre-scaled), k, v in [b][h][n][32] layout.
// MODE 1: proj — write f32 + bias to Cout.
template<int MODE>
__global__ __launch_bounds__(256)
void gemm_tf32(const float* __restrict__ A, const float* __restrict__ W,
               const float* __restrict__ bias, float* __restrict__ Cout, int Ntotal) {
    extern __shared__ float sm[];
    float* As = sm;               // [128][68]
    float* Bs = sm + 128 * 68;    // [128][68]
    const int tid  = threadIdx.x;
    const int warp = tid >> 5, lane = tid & 31;
    const int g = lane >> 2, t = lane & 3;
    const int wm = warp >> 1, wn = warp & 1;
    const int bm = blockIdx.x, bn = blockIdx.y;

    float acc[2][8][4];
    #pragma unroll
    for (int i = 0; i < 2; i++)
        #pragma unroll
        for (int j = 0; j < 8; j++)
            #pragma unroll
            for (int k = 0; k < 4; k++) acc[i][j][k] = 0.f;

    for (int kc = 0; kc < 4; kc++) {
        {
            int r  = tid >> 4;            // 0..15
            int c4 = (tid & 15) * 4;      // 0..60
            const float* Ag = A + ((size_t)(bm * 128 + r)) * 256 + kc * 64 + c4;
            const float* Bg = W + ((size_t)(bn * 128 + r)) * 256 + kc * 64 + c4;
            #pragma unroll
            for (int it = 0; it < 8; it++) {
                float4 av = *(const float4*)(Ag + (size_t)it * 16 * 256);
                float4 bv = *(const float4*)(Bg + (size_t)it * 16 * 256);
                float* ad = &As[(r + it * 16) * 68 + c4];
                float* bd = &Bs[(r + it * 16) * 68 + c4];
                ad[0] = tf32r(av.x); ad[1] = tf32r(av.y); ad[2] = tf32r(av.z); ad[3] = tf32r(av.w);
                bd[0] = tf32r(bv.x); bd[1] = tf32r(bv.y); bd[2] = tf32r(bv.z); bd[3] = tf32r(bv.w);
            }
        }
        __syncthreads();
        #pragma unroll
        for (int ks = 0; ks < 8; ks++) {
            int k0 = ks * 8;
            uint32_t aF[2][4];
            #pragma unroll
            for (int mt = 0; mt < 2; mt++) {
                int m0 = wm * 32 + mt * 16;
                aF[mt][0] = __float_as_uint(As[(m0 + g    ) * 68 + k0 + t    ]);
                aF[mt][1] = __float_as_uint(As[(m0 + g + 8) * 68 + k0 + t    ]);
                aF[mt][2] = __float_as_uint(As[(m0 + g    ) * 68 + k0 + t + 4]);
                aF[mt][3] = __float_as_uint(As[(m0 + g + 8) * 68 + k0 + t + 4]);
            }
            #pragma unroll
            for (int nt = 0; nt < 8; nt++) {
                int n0 = wn * 64 + nt * 8;
                uint32_t b0 = __float_as_uint(Bs[(n0 + g) * 68 + k0 + t    ]);
                uint32_t b1 = __float_as_uint(Bs[(n0 + g) * 68 + k0 + t + 4]);
                mma_tf32(acc[0][nt][0], acc[0][nt][1], acc[0][nt][2], acc[0][nt][3],
                         aF[0][0], aF[0][1], aF[0][2], aF[0][3], b0, b1);
                mma_tf32(acc[1][nt][0], acc[1][nt][1], acc[1][nt][2], acc[1][nt][3],
                         aF[1][0], aF[1][1], aF[1][2], aF[1][3], b0, b1);
            }
        }
        __syncthreads();
    }

    if (MODE == 0) {
        const int which = bn >> 1;
        __nv_bfloat16* dst = (which == 0) ? g_q : (which == 1) ? g_k : g_v;
        const float sc = (which == 0) ? QK_SCALE : 1.f;
        #pragma unroll
        for (int mt = 0; mt < 2; mt++) {
            int r0 = bm * 128 + wm * 32 + mt * 16 + g;
            int r8 = r0 + 8;
            int b0i = r0 / NSEQ, n0 = r0 - b0i * NSEQ;
            int b8i = r8 / NSEQ, n8 = r8 - b8i * NSEQ;
            #pragma unroll
            for (int nt = 0; nt < 8; nt++) {
                int c0 = bn * 128 + wn * 64 + nt * 8 + 2 * t;
                int h = (c0 >> 5) & 7, d = c0 & 31;
                uint32_t lo = pack_bf16(acc[mt][nt][0] * sc, acc[mt][nt][1] * sc);
                uint32_t hi = pack_bf16(acc[mt][nt][2] * sc, acc[mt][nt][3] * sc);
                *(uint32_t*)&dst[((size_t)(b0i * 8 + h) * NSEQ + n0) * 32 + d] = lo;
                *(uint32_t*)&dst[((size_t)(b8i * 8 + h) * NSEQ + n8) * 32 + d] = hi;
            }
        }
    } else {
        #pragma unroll
        for (int mt = 0; mt < 2; mt++) {
            int r0 = bm * 128 + wm * 32 + mt * 16 + g;
            #pragma unroll
            for (int nt = 0; nt < 8; nt++) {
                int c0 = bn * 128 + wn * 64 + nt * 8 + 2 * t;
                float bb0 = bias[c0], bb1 = bias[c0 + 1];
                float2 v0 = make_float2(acc[mt][nt][0] + bb0, acc[mt][nt][1] + bb1);
                float2 v1 = make_float2(acc[mt][nt][2] + bb0, acc[mt][nt][3] + bb1);
                *(float2*)&Cout[(size_t)r0       * Ntotal + c0] = v0;
                *(float2*)&Cout[(size_t)(r0 + 8) * Ntotal + c0] = v1;
            }
        }
    }
}

// ---------------- 3) flash attention: 4 warps, 32 Q-rows per warp ----------------
// smem: Kbuf[p] @ p*20480, Vbuf[p] @ p*20480+10240 (pitch 80B, 128 rows x 64B data)
//       MAdd @ 40960 (512B)   -> total 41472B
#define KV_PITCH 80
#define SM_STAGE 20480
#define SM_MA    40960
#define ATTN_SMEM 41472

__global__ void __launch_bounds__(128, 2) attn_kernel() {
    extern __shared__ char smx[];
    const uint32_t sbase = (uint32_t)__cvta_generic_to_shared(smx);
    float* MAdd = (float*)(smx + SM_MA);

    const int tid  = threadIdx.x;
    const int warp = tid >> 5, lane = tid & 31;
    const int g = lane >> 2, t = lane & 3;
    const int qt = blockIdx.x, bh = blockIdx.y;
    const int b = bh >> 3, h = bh & 7;
    const int qbase = qt * 128;

    // 4 rows per thread: sub0 -> r[0]=+g, r[1]=+g+8 ; sub1 -> r[2]=+g+16, r[3]=+g+24
    int r[4], rc[4];
    #pragma unroll
    for (int i = 0; i < 4; i++) {
        r[i]  = qbase + warp * 32 + g + i * 8;
        rc[i] = min(r[i], NSEQ - 1);
    }

    const __nv_bfloat16* kbase = g_k + (size_t)bh * NSEQ * 32;
    const __nv_bfloat16* vbase = g_v + (size_t)bh * NSEQ * 32;

    // Q fragments (pre-scaled bf16, direct load): aq[sub][kk][frag]
    uint32_t aq[2][2][4];
    #pragma unroll
    for (int sub = 0; sub < 2; sub++) {
        const __nv_bfloat16* qlo = g_q + ((size_t)bh * NSEQ + rc[2 * sub])     * 32;
        const __nv_bfloat16* qhi = g_q + ((size_t)bh * NSEQ + rc[2 * sub + 1]) * 32;
        #pragma unroll
        for (int kk = 0; kk < 2; kk++) {
            aq[sub][kk][0] = *(const uint32_t*)(qlo + kk * 16 + 2 * t);
            aq[sub][kk][1] = *(const uint32_t*)(qhi + kk * 16 + 2 * t);
            aq[sub][kk][2] = *(const uint32_t*)(qlo + kk * 16 + 2 * t + 8);
            aq[sub][kk][3] = *(const uint32_t*)(qhi + kk * 16 + 2 * t + 8);
        }
    }

    // bias fragment row pointers
    const __nv_bfloat16* bptr[4];
    #pragma unroll
    for (int i = 0; i < 4; i++)
        bptr[i] = g_bias + ((size_t)h * NSEQ + rc[i]) * NPAD + 2 * t;

    // ldmatrix lane addressing (warp-independent)
    const uint32_t lk_row = (lane & 7);
    const uint32_t lk_grp = (lane >> 3);
    const uint32_t offK = lk_row * KV_PITCH + lk_grp * 16;
    const uint32_t offV = ((lk_grp & 1) * 8 + lk_row) * KV_PITCH + (lk_grp >> 1) * 16 + 10240;

    float accO[2][4][4];
    #pragma unroll
    for (int s = 0; s < 2; s++)
        #pragma unroll
        for (int i = 0; i < 4; i++)
            #pragma unroll
            for (int j = 0; j < 4; j++) accO[s][i][j] = 0.f;
    float m[4] = {-1e30f, -1e30f, -1e30f, -1e30f};   // [sub*2 + half]
    float l[4] = {0.f, 0.f, 0.f, 0.f};

    // stage tile kt into buffer p via cp.async
    auto stage = [&](int kt, int p) {
        const int kb = kt * 128;
        #pragma unroll
        for (int it = 0; it < 4; it++) {
            int idx = tid + it * 128;          // 0..511
            int row = idx >> 2, ch = idx & 3;  // 128 rows x 4 chunks of 16B
            int key = kb + row;
            int sz = (key < NSEQ) ? 16 : 0;
            uint32_t s0 = sbase + p * SM_STAGE + row * KV_PITCH + ch * 16;
            cp_async16(s0,         kbase + (size_t)key * 32 + ch * 8, sz);
            cp_async16(s0 + 10240, vbase + (size_t)key * 32 + ch * 8, sz);
        }
        cp_commit();
    };

    stage(0, 0);

    for (int kt = 0; kt < 10; kt++) {
        const int p  = kt & 1;
        const int kb = kt * 128;
        if (kt < 9) stage(kt + 1, p ^ 1);
        {
            int key = kb + tid;
            MAdd[tid] = (key < NSEQ) ? g_madd[b * NSEQ + key] : -3e38f;
        }
        if (kt < 9) cp_wait<1>(); else cp_wait<0>();
        __syncthreads();

        const uint32_t addrK = sbase + p * SM_STAGE + offK;
        const uint32_t addrV = sbase + p * SM_STAGE + offV;

        // --- S = Q K^T : each K ldsm feeds both sub-tiles (4 mmas) ---
        float S[2][16][4];
        #pragma unroll
        for (int nt = 0; nt < 16; nt++) {
            uint32_t b0, b1, b2, b3;
            ldsm_x4(b0, b1, b2, b3, addrK + nt * (8 * KV_PITCH));
            #pragma unroll
            for (int sub = 0; sub < 2; sub++) {
                S[sub][nt][0] = S[sub][nt][1] = S[sub][nt][2] = S[sub][nt][3] = 0.f;
                mma_bf16(S[sub][nt][0], S[sub][nt][1], S[sub][nt][2], S[sub][nt][3],
                         aq[sub][0][0], aq[sub][0][1], aq[sub][0][2], aq[sub][0][3], b0, b1);
                mma_bf16(S[sub][nt][0], S[sub][nt][1], S[sub][nt][2], S[sub][nt][3],
                         aq[sub][1][0], aq[sub][1][1], aq[sub][1][2], aq[sub][1][3], b2, b3);
            }
        }
        // --- + bias (global) + mask (smem); row max ---
        float tmax[4] = {-3e38f, -3e38f, -3e38f, -3e38f};
        #pragma unroll
        for (int nt = 0; nt < 16; nt++) {
            float2 mm = *(float2*)&MAdd[nt * 8 + 2 * t];
            #pragma unroll
            for (int sub = 0; sub < 2; sub++) {
                float2 bl  = unpack_bf16(*(const uint32_t*)(bptr[2 * sub]     + kb + nt * 8));
                float2 bh2 = unpack_bf16(*(const uint32_t*)(bptr[2 * sub + 1] + kb + nt * 8));
                S[sub][nt][0] += bl.x + mm.x;   S[sub][nt][1] += bl.y + mm.y;
                S[sub][nt][2] += bh2.x + mm.x;  S[sub][nt][3] += bh2.y + mm.y;
                tmax[2 * sub]     = fmaxf(tmax[2 * sub],     fmaxf(S[sub][nt][0], S[sub][nt][1]));
                tmax[2 * sub + 1] = fmaxf(tmax[2 * sub + 1], fmaxf(S[sub][nt][2], S[sub][nt][3]));
            }
        }
        float al[4], sums[4] = {0.f, 0.f, 0.f, 0.f};
        #pragma unroll
        for (int i = 0; i < 4; i++) {
            tmax[i] = fmaxf(tmax[i], __shfl_xor_sync(0xffffffffu, tmax[i], 1));
            tmax[i] = fmaxf(tmax[i], __shfl_xor_sync(0xffffffffu, tmax[i], 2));
            float mn = fmaxf(m[i], tmax[i]);
            al[i] = __expf(m[i] - mn);
            m[i] = mn;
        }
        #pragma unroll
        for (int nt = 0; nt < 16; nt++) {
            #pragma unroll
            for (int sub = 0; sub < 2; sub++) {
                S[sub][nt][0] = __expf(S[sub][nt][0] - m[2 * sub]);
                S[sub][nt][1] = __expf(S[sub][nt][1] - m[2 * sub]);
                S[sub][nt][2] = __expf(S[sub][nt][2] - m[2 * sub + 1]);
                S[sub][nt][3] = __expf(S[sub][nt][3] - m[2 * sub + 1]);
                sums[2 * sub]     += S[sub][nt][0] + S[sub][nt][1];
                sums[2 * sub + 1] += S[sub][nt][2] + S[sub][nt][3];
            }
        }
        #pragma unroll
        for (int i = 0; i < 4; i++) {
            sums[i] += __shfl_xor_sync(0xffffffffu, sums[i], 1);
            sums[i] += __shfl_xor_sync(0xffffffffu, sums[i], 2);
            l[i] = l[i] * al[i] + sums[i];
        }
        #pragma unroll
        for (int sub = 0; sub < 2; sub++)
            #pragma unroll
            for (int no = 0; no < 4; no++) {
                accO[sub][no][0] *= al[2 * sub];     accO[sub][no][1] *= al[2 * sub];
                accO[sub][no][2] *= al[2 * sub + 1]; accO[sub][no][3] *= al[2 * sub + 1];
            }
        // --- O += P V : each V ldsm feeds both sub-tiles ---
        #pragma unroll
        for (int j = 0; j < 8; j++) {
            uint32_t a[2][4];
            #pragma unroll
            for (int sub = 0; sub < 2; sub++) {
                a[sub][0] = pack_bf16(S[sub][2 * j][0],     S[sub][2 * j][1]);
                a[sub][1] = pack_bf16(S[sub][2 * j][2],     S[sub][2 * j][3]);
                a[sub][2] = pack_bf16(S[sub][2 * j + 1][0], S[sub][2 * j + 1][1]);
                a[sub][3] = pack_bf16(S[sub][2 * j + 1][2], S[sub][2 * j + 1][3]);
            }
            #pragma unroll
            for (int nob = 0; nob < 4; nob += 2) {
                uint32_t v0, v1, v2, v3;
                ldsm_x4t(v0, v1, v2, v3, addrV + j * (16 * KV_PITCH) + nob * 16);
                #pragma unroll
                for (int sub = 0; sub < 2; sub++) {
                    mma_bf16(accO[sub][nob][0], accO[sub][nob][1],
                             accO[sub][nob][2], accO[sub][nob][3],
                             a[sub][0], a[sub][1], a[sub][2], a[sub][3], v0, v1);
                    mma_bf16(accO[sub][nob + 1][0], accO[sub][nob + 1][1],
                             accO[sub][nob + 1][2], accO[sub][nob + 1][3],
                             a[sub][0], a[sub][1], a[sub][2], a[sub][3], v2, v3);
                }
            }
        }
        __syncthreads();
    }

    #pragma unroll
    for (int sub = 0; sub < 2; sub++) {
        float il = 1.f / l[2 * sub];
        float ih = 1.f / l[2 * sub + 1];
        if (r[2 * sub] < NSEQ) {
            #pragma unroll
            for (int no = 0; no < 4; no++) {
                float2 v = make_float2(accO[sub][no][0] * il, accO[sub][no][1] * il);
                *(float2*)&g_att[((size_t)b * NSEQ + r[2 * sub]) * 256 + h * 32 + no * 8 + 2 * t] = v;
            }
        }
        if (r[2 * sub + 1] < NSEQ) {
            #pragma unroll
            for (int no = 0; no < 4; no++) {
                float2 v = make_float2(accO[sub][no][2] * ih, accO[sub][no][3] * ih);
                *(float2*)&g_att[((size_t)b * NSEQ + r[2 * sub + 1]) * 256 + h * 32 + no * 8 + 2 * t] = v;
            }
        }
    }
}

// ---------------- launch ----------------
extern "C" void kernel_launch(void* const* d_in, const int* in_sizes, int n_in,
                              void* d_out, int out_size) {
    const float*         x       = (const float*)d_in[0];
    const unsigned char* mask    = (const unsigned char*)d_in[1];
    const float*         w_qkv   = (const float*)d_in[2];
    const float*         w_proj  = (const float*)d_in[3];
    const float*         b_proj  = (const float*)d_in[4];
    const float*         rpb     = (const float*)d_in[5];
    const int*           relidx  = (const int*)d_in[6];
    const int num_rel = in_sizes[5] / H_;

    const int GEMM_SMEM = 2 * 128 * 68 * 4;           // 69632
    cudaFuncSetAttribute(gemm_tf32<0>, cudaFuncAttributeMaxDynamicSharedMemorySize, GEMM_SMEM);
    cudaFuncSetAttribute(gemm_tf32<1>, cudaFuncAttributeMaxDynamicSharedMemorySize, GEMM_SMEM);
    cudaFuncSetAttribute(attn_kernel,  cudaFuncAttributeMaxDynamicSharedMemorySize, ATTN_SMEM);

    void* p_att = nullptr;
    cudaGetSymbolAddress(&p_att, g_att);

    mask_kernel<<<1, 256>>>(mask);
    bias_kernel<<<(NSEQ * NPAD + 255) / 256, 256>>>(relidx, rpb, num_rel);
    gemm_tf32<0><<<dim3(MROWS / 128, 768 / 128), 256, GEMM_SMEM>>>(
        x, w_qkv, nullptr, nullptr, 768);
    attn_kernel<<<dim3(10, B_ * H_), 128, ATTN_SMEM>>>();
    gemm_tf32<1><<<dim3(MROWS / 128, 256 / 128), 256, GEMM_SMEM>>>(
        (const float*)p_att, w_proj, b_proj, (float*)d_out, 256);
}

// round 7
// speedup vs baseline: 1.9278x; 1.2196x over previous
#include <cuda_runtime.h>
#include <cuda_bf16.h>
#include <cstdint>

#define B_    16
#define NSEQ  1168
#define H_    8
#define DH    32
#define C_    256
#define NPAD  1280
#define MROWS (B_*NSEQ)   // 18688 = 146*128
#define LOG2E 1.4426950408889634f
#define QK_SCALE (0.1767766952966369f * LOG2E)   // 32^-0.5 * log2(e), folded into q

// ---------------- scratch (device globals; no runtime alloc) ----------------
__device__ __align__(16) __nv_bfloat16  g_q[(size_t)B_ * H_ * NSEQ * DH];
__device__ __align__(16) __nv_bfloat16  g_k[(size_t)B_ * H_ * NSEQ * DH];
__device__ __align__(16) __nv_bfloat16  g_v[(size_t)B_ * H_ * NSEQ * DH];
__device__ __align__(16) __nv_bfloat16  g_bias[(size_t)H_ * NSEQ * NPAD];  // reordered, *log2e
__device__ float          g_att[(size_t)MROWS * C_];
__device__ float          g_madd[(size_t)B_ * NSEQ];

// ---------------- helpers ----------------
__device__ __forceinline__ float tf32r(float x) {
    uint32_t u;
    asm("cvt.rna.tf32.f32 %0, %1;" : "=r"(u) : "f"(x));
    return __uint_as_float(u);
}
__device__ __forceinline__ float ex2f(float x) {
    float y;
    asm("ex2.approx.ftz.f32 %0, %1;" : "=f"(y) : "f"(x));
    return y;
}
__device__ __forceinline__ uint32_t pack_bf16(float x, float y) {
    __nv_bfloat162 h = __floats2bfloat162_rn(x, y);
    return *reinterpret_cast<uint32_t*>(&h);
}
__device__ __forceinline__ float2 unpack_bf16(uint32_t u) {
    __nv_bfloat162 h = *reinterpret_cast<__nv_bfloat162*>(&u);
    return __bfloat1622float2(h);
}
__device__ __forceinline__ uint32_t u4w(const uint4& v, int w) {
    return w == 0 ? v.x : w == 1 ? v.y : w == 2 ? v.z : v.w;
}
__device__ __forceinline__ void mma_tf32(float& d0, float& d1, float& d2, float& d3,
                                         uint32_t a0, uint32_t a1, uint32_t a2, uint32_t a3,
                                         uint32_t b0, uint32_t b1) {
    asm volatile("mma.sync.aligned.m16n8k8.row.col.f32.tf32.tf32.f32 "
                 "{%0,%1,%2,%3},{%4,%5,%6,%7},{%8,%9},{%0,%1,%2,%3};"
                 : "+f"(d0), "+f"(d1), "+f"(d2), "+f"(d3)
                 : "r"(a0), "r"(a1), "r"(a2), "r"(a3), "r"(b0), "r"(b1));
}
__device__ __forceinline__ void mma_bf16(float& d0, float& d1, float& d2, float& d3,
                                         uint32_t a0, uint32_t a1, uint32_t a2, uint32_t a3,
                                         uint32_t b0, uint32_t b1) {
    asm volatile("mma.sync.aligned.m16n8k16.row.col.f32.bf16.bf16.f32 "
                 "{%0,%1,%2,%3},{%4,%5,%6,%7},{%8,%9},{%0,%1,%2,%3};"
                 : "+f"(d0), "+f"(d1), "+f"(d2), "+f"(d3)
                 : "r"(a0), "r"(a1), "r"(a2), "r"(a3), "r"(b0), "r"(b1));
}
__device__ __forceinline__ void ldsm_x4(uint32_t& r0, uint32_t& r1, uint32_t& r2, uint32_t& r3,
                                        uint32_t addr) {
    asm volatile("ldmatrix.sync.aligned.m8n8.x4.shared.b16 {%0,%1,%2,%3}, [%4];"
                 : "=r"(r0), "=r"(r1), "=r"(r2), "=r"(r3) : "r"(addr));
}
__device__ __forceinline__ void ldsm_x4t(uint32_t& r0, uint32_t& r1, uint32_t& r2, uint32_t& r3,
                                         uint32_t addr) {
    asm volatile("ldmatrix.sync.aligned.m8n8.x4.trans.shared.b16 {%0,%1,%2,%3}, [%4];"
                 : "=r"(r0), "=r"(r1), "=r"(r2), "=r"(r3) : "r"(addr));
}
__device__ __forceinline__ void cp_async16(uint32_t saddr, const void* gaddr, int srcsize) {
    asm volatile("cp.async.ca.shared.global [%0], [%1], 16, %2;"
                 :: "r"(saddr), "l"(gaddr), "r"(srcsize) : "memory");
}
__device__ __forceinline__ void cp_commit() {
    asm volatile("cp.async.commit_group;" ::: "memory");
}
template<int N> __device__ __forceinline__ void cp_wait() {
    asm volatile("cp.async.wait_group %0;" :: "n"(N) : "memory");
}

// ---------------- 0) mask canonicalization (dtype auto-detect) ----------------
__global__ void mask_kernel(const unsigned char* __restrict__ mraw) {
    __shared__ int s_pos[4];
    if (threadIdx.x < 4) s_pos[threadIdx.x] = 0;
    __syncthreads();
    int loc[4] = {0, 0, 0, 0};
    for (int i = threadIdx.x; i < 4096; i += blockDim.x)
        if (mraw[i]) loc[i & 3] = 1;
    #pragma unroll
    for (int p = 0; p < 4; p++)
        if (loc[p]) atomicOr(&s_pos[p], 1);
    __syncthreads();
    int mode;                 // 0=uint8, 1=int32, 2=float32
    if (s_pos[1]) mode = 0;
    else if (s_pos[2] | s_pos[3]) mode = 2;
    else mode = 1;
    const int total = B_ * NSEQ;
    for (int i = threadIdx.x; i < total; i += blockDim.x) {
        bool m;
        if (mode == 0)      m = mraw[i] != 0;
        else if (mode == 1) m = ((const int*)mraw)[i] != 0;
        else                m = ((const float*)mraw)[i] != 0.f;
        g_madd[i] = m ? -3e38f : 0.f;
    }
}

// ---------------- 1) bias gather: *log2e, fragment-ordered within 128-key blocks ----
// dest pos within block: (t 0..3)[x32] (nt 0..15)[x2] (pair e 0..1)
__global__ void bias_kernel(const int* __restrict__ rel_index,
                            const float* __restrict__ rpb, int num_rel) {
    int idx = blockIdx.x * blockDim.x + threadIdx.x;
    if (idx >= NSEQ * NPAD) return;
    int i = idx / NPAD;
    int j = idx - i * NPAD;
    int kt = j >> 7, rem = j & 127;
    int nt = rem >> 3, tt = (rem >> 1) & 3, e = rem & 1;
    int pos = (kt << 7) + (tt << 5) + (nt << 1) + e;
    if (j < NSEQ) {
        int r = rel_index[i * NSEQ + j];
        #pragma unroll
        for (int h = 0; h < H_; h++)
            g_bias[((size_t)h * NSEQ + i) * NPAD + pos] =
                __float2bfloat16(rpb[h * num_rel + r] * LOG2E);
    } else {
        #pragma unroll
        for (int h = 0; h < H_; h++)
            g_bias[((size_t)h * NSEQ + i) * NPAD + pos] = __float2bfloat16(0.f);
    }
}

// ---------------- 2/4) tf32 GEMM: C[M,Nt] = A[M,256] * W[Nt,256]^T ----------------
template<int MODE>
__global__ __launch_bounds__(256)
void gemm_tf32(const float* __restrict__ A, const float* __restrict__ W,
               const float* __restrict__ bias, float* __restrict__ Cout, int Ntotal) {
    extern __shared__ float sm[];
    float* As = sm;               // [128][68]
    float* Bs = sm + 128 * 68;    // [128][68]
    const int tid  = threadIdx.x;
    const int warp = tid >> 5, lane = tid & 31;
    const int g = lane >> 2, t = lane & 3;
    const int wm = warp >> 1, wn = warp & 1;
    const int bm = blockIdx.x, bn = blockIdx.y;

    float acc[2][8][4];
    #pragma unroll
    for (int i = 0; i < 2; i++)
        #pragma unroll
        for (int j = 0; j < 8; j++)
            #pragma unroll
            for (int k = 0; k < 4; k++) acc[i][j][k] = 0.f;

    for (int kc = 0; kc < 4; kc++) {
        {
            int r  = tid >> 4;
            int c4 = (tid & 15) * 4;
            const float* Ag = A + ((size_t)(bm * 128 + r)) * 256 + kc * 64 + c4;
            const float* Bg = W + ((size_t)(bn * 128 + r)) * 256 + kc * 64 + c4;
            #pragma unroll
            for (int it = 0; it < 8; it++) {
                float4 av = *(const float4*)(Ag + (size_t)it * 16 * 256);
                float4 bv = *(const float4*)(Bg + (size_t)it * 16 * 256);
                float* ad = &As[(r + it * 16) * 68 + c4];
                float* bd = &Bs[(r + it * 16) * 68 + c4];
                ad[0] = tf32r(av.x); ad[1] = tf32r(av.y); ad[2] = tf32r(av.z); ad[3] = tf32r(av.w);
                bd[0] = tf32r(bv.x); bd[1] = tf32r(bv.y); bd[2] = tf32r(bv.z); bd[3] = tf32r(bv.w);
            }
        }
        __syncthreads();
        #pragma unroll
        for (int ks = 0; ks < 8; ks++) {
            int k0 = ks * 8;
            uint32_t aF[2][4];
            #pragma unroll
            for (int mt = 0; mt < 2; mt++) {
                int m0 = wm * 32 + mt * 16;
                aF[mt][0] = __float_as_uint(As[(m0 + g    ) * 68 + k0 + t    ]);
                aF[mt][1] = __float_as_uint(As[(m0 + g + 8) * 68 + k0 + t    ]);
                aF[mt][2] = __float_as_uint(As[(m0 + g    ) * 68 + k0 + t + 4]);
                aF[mt][3] = __float_as_uint(As[(m0 + g + 8) * 68 + k0 + t + 4]);
            }
            #pragma unroll
            for (int nt = 0; nt < 8; nt++) {
                int n0 = wn * 64 + nt * 8;
                uint32_t b0 = __float_as_uint(Bs[(n0 + g) * 68 + k0 + t    ]);
                uint32_t b1 = __float_as_uint(Bs[(n0 + g) * 68 + k0 + t + 4]);
                mma_tf32(acc[0][nt][0], acc[0][nt][1], acc[0][nt][2], acc[0][nt][3],
                         aF[0][0], aF[0][1], aF[0][2], aF[0][3], b0, b1);
                mma_tf32(acc[1][nt][0], acc[1][nt][1], acc[1][nt][2], acc[1][nt][3],
                         aF[1][0], aF[1][1], aF[1][2], aF[1][3], b0, b1);
            }
        }
        __syncthreads();
    }

    if (MODE == 0) {
        const int which = bn >> 1;
        __nv_bfloat16* dst = (which == 0) ? g_q : (which == 1) ? g_k : g_v;
        const float sc = (which == 0) ? QK_SCALE : 1.f;
        #pragma unroll
        for (int mt = 0; mt < 2; mt++) {
            int r0 = bm * 128 + wm * 32 + mt * 16 + g;
            int r8 = r0 + 8;
            int b0i = r0 / NSEQ, n0 = r0 - b0i * NSEQ;
            int b8i = r8 / NSEQ, n8 = r8 - b8i * NSEQ;
            #pragma unroll
            for (int nt = 0; nt < 8; nt++) {
                int c0 = bn * 128 + wn * 64 + nt * 8 + 2 * t;
                int h = (c0 >> 5) & 7, d = c0 & 31;
                uint32_t lo = pack_bf16(acc[mt][nt][0] * sc, acc[mt][nt][1] * sc);
                uint32_t hi = pack_bf16(acc[mt][nt][2] * sc, acc[mt][nt][3] * sc);
                *(uint32_t*)&dst[((size_t)(b0i * 8 + h) * NSEQ + n0) * 32 + d] = lo;
                *(uint32_t*)&dst[((size_t)(b8i * 8 + h) * NSEQ + n8) * 32 + d] = hi;
            }
        }
    } else {
        #pragma unroll
        for (int mt = 0; mt < 2; mt++) {
            int r0 = bm * 128 + wm * 32 + mt * 16 + g;
            #pragma unroll
            for (int nt = 0; nt < 8; nt++) {
                int c0 = bn * 128 + wn * 64 + nt * 8 + 2 * t;
                float bb0 = bias[c0], bb1 = bias[c0 + 1];
                float2 v0 = make_float2(acc[mt][nt][0] + bb0, acc[mt][nt][1] + bb1);
                float2 v1 = make_float2(acc[mt][nt][2] + bb0, acc[mt][nt][3] + bb1);
                *(float2*)&Cout[(size_t)r0       * Ntotal + c0] = v0;
                *(float2*)&Cout[(size_t)(r0 + 8) * Ntotal + c0] = v1;
            }
        }
    }
}

// ---------------- 3) flash attention: 4 warps x 32 Q-rows, 64-key half-tiles ----------------
#define KV_PITCH 80
#define SM_STAGE 20480
#define SM_MA    40960
#define ATTN_SMEM 41472

__global__ void __launch_bounds__(128, 3) attn_kernel() {
    extern __shared__ char smx[];
    const uint32_t sbase = (uint32_t)__cvta_generic_to_shared(smx);
    float* MAdd = (float*)(smx + SM_MA);

    const int tid  = threadIdx.x;
    const int warp = tid >> 5, lane = tid & 31;
    const int g = lane >> 2, t = lane & 3;
    const int qt = blockIdx.x, bh = blockIdx.y;
    const int b = bh >> 3, h = bh & 7;
    const int qbase = qt * 128;

    int r[4], rc[4];
    #pragma unroll
    for (int i = 0; i < 4; i++) {
        r[i]  = qbase + warp * 32 + g + i * 8;
        rc[i] = min(r[i], NSEQ - 1);
    }

    const __nv_bfloat16* kbase = g_k + (size_t)bh * NSEQ * 32;
    const __nv_bfloat16* vbase = g_v + (size_t)bh * NSEQ * 32;

    uint32_t aq[2][2][4];
    #pragma unroll
    for (int sub = 0; sub < 2; sub++) {
        const __nv_bfloat16* qlo = g_q + ((size_t)bh * NSEQ + rc[2 * sub])     * 32;
        const __nv_bfloat16* qhi = g_q + ((size_t)bh * NSEQ + rc[2 * sub + 1]) * 32;
        #pragma unroll
        for (int kk = 0; kk < 2; kk++) {
            aq[sub][kk][0] = *(const uint32_t*)(qlo + kk * 16 + 2 * t);
            aq[sub][kk][1] = *(const uint32_t*)(qhi + kk * 16 + 2 * t);
            aq[sub][kk][2] = *(const uint32_t*)(qlo + kk * 16 + 2 * t + 8);
            aq[sub][kk][3] = *(const uint32_t*)(qhi + kk * 16 + 2 * t + 8);
        }
    }

    // reordered bias row pointers (element units); per-tile offset = kb + half*16 + qq*8
    const __nv_bfloat16* bptr[4];
    #pragma unroll
    for (int i = 0; i < 4; i++)
        bptr[i] = g_bias + ((size_t)h * NSEQ + rc[i]) * NPAD + t * 32;

    const uint32_t lk_row = (lane & 7);
    const uint32_t lk_grp = (lane >> 3);
    const uint32_t offK = lk_row * KV_PITCH + lk_grp * 16;
    const uint32_t offV = ((lk_grp & 1) * 8 + lk_row) * KV_PITCH + (lk_grp >> 1) * 16 + 10240;

    float accO[2][4][4];
    #pragma unroll
    for (int s = 0; s < 2; s++)
        #pragma unroll
        for (int i = 0; i < 4; i++)
            #pragma unroll
            for (int j = 0; j < 4; j++) accO[s][i][j] = 0.f;
    float m[4] = {-1e30f, -1e30f, -1e30f, -1e30f};
    float l[4] = {0.f, 0.f, 0.f, 0.f};

    auto stage = [&](int kt, int p) {
        const int kb = kt * 128;
        #pragma unroll
        for (int it = 0; it < 4; it++) {
            int idx = tid + it * 128;
            int row = idx >> 2, ch = idx & 3;
            int key = kb + row;
            int sz = (key < NSEQ) ? 16 : 0;
            uint32_t s0 = sbase + p * SM_STAGE + row * KV_PITCH + ch * 16;
            cp_async16(s0,         kbase + (size_t)key * 32 + ch * 8, sz);
            cp_async16(s0 + 10240, vbase + (size_t)key * 32 + ch * 8, sz);
        }
        cp_commit();
    };

    stage(0, 0);

    for (int kt = 0; kt < 10; kt++) {
        const int p  = kt & 1;
        const int kb = kt * 128;
        if (kt < 9) stage(kt + 1, p ^ 1);
        {
            int key = kb + tid;
            MAdd[tid] = (key < NSEQ) ? g_madd[b * NSEQ + key] : -3e38f;
        }
        if (kt < 9) cp_wait<1>(); else cp_wait<0>();
        __syncthreads();

        const uint32_t addrK = sbase + p * SM_STAGE + offK;
        const uint32_t addrV = sbase + p * SM_STAGE + offV;

        #pragma unroll
        for (int half = 0; half < 2; half++) {
            // --- S = Q K^T over 64 keys ---
            float S[2][8][4];
            #pragma unroll
            for (int ntl = 0; ntl < 8; ntl++) {
                uint32_t b0, b1, b2, b3;
                ldsm_x4(b0, b1, b2, b3, addrK + (half * 8 + ntl) * (8 * KV_PITCH));
                #pragma unroll
                for (int sub = 0; sub < 2; sub++) {
                    S[sub][ntl][0] = S[sub][ntl][1] = S[sub][ntl][2] = S[sub][ntl][3] = 0.f;
                    mma_bf16(S[sub][ntl][0], S[sub][ntl][1], S[sub][ntl][2], S[sub][ntl][3],
                             aq[sub][0][0], aq[sub][0][1], aq[sub][0][2], aq[sub][0][3], b0, b1);
                    mma_bf16(S[sub][ntl][0], S[sub][ntl][1], S[sub][ntl][2], S[sub][ntl][3],
                             aq[sub][1][0], aq[sub][1][1], aq[sub][1][2], aq[sub][1][3], b2, b3);
                }
            }
            // --- bias (contiguous fragment loads) + mask; row max ---
            float tmax[4] = {-3e38f, -3e38f, -3e38f, -3e38f};
            #pragma unroll
            for (int qq = 0; qq < 2; qq++) {
                uint4 bu[4];
                #pragma unroll
                for (int i = 0; i < 4; i++)
                    bu[i] = *(const uint4*)(bptr[i] + kb + half * 16 + qq * 8);
                #pragma unroll
                for (int w = 0; w < 4; w++) {
                    int ntl = qq * 4 + w;
                    float2 mm = *(float2*)&MAdd[(half * 8 + ntl) * 8 + 2 * t];
                    #pragma unroll
                    for (int sub = 0; sub < 2; sub++) {
                        float2 bl  = unpack_bf16(u4w(bu[2 * sub],     w));
                        float2 bh2 = unpack_bf16(u4w(bu[2 * sub + 1], w));
                        S[sub][ntl][0] += bl.x + mm.x;   S[sub][ntl][1] += bl.y + mm.y;
                        S[sub][ntl][2] += bh2.x + mm.x;  S[sub][ntl][3] += bh2.y + mm.y;
                        tmax[2 * sub]     = fmaxf(tmax[2 * sub],     fmaxf(S[sub][ntl][0], S[sub][ntl][1]));
                        tmax[2 * sub + 1] = fmaxf(tmax[2 * sub + 1], fmaxf(S[sub][ntl][2], S[sub][ntl][3]));
                    }
                }
            }
            float al[4], sums[4] = {0.f, 0.f, 0.f, 0.f};
            #pragma unroll
            for (int i = 0; i < 4; i++) {
                tmax[i] = fmaxf(tmax[i], __shfl_xor_sync(0xffffffffu, tmax[i], 1));
                tmax[i] = fmaxf(tmax[i], __shfl_xor_sync(0xffffffffu, tmax[i], 2));
                float mn = fmaxf(m[i], tmax[i]);
                al[i] = ex2f(m[i] - mn);
                m[i] = mn;
            }
            #pragma unroll
            for (int ntl = 0; ntl < 8; ntl++) {
                #pragma unroll
                for (int sub = 0; sub < 2; sub++) {
                    S[sub][ntl][0] = ex2f(S[sub][ntl][0] - m[2 * sub]);
                    S[sub][ntl][1] = ex2f(S[sub][ntl][1] - m[2 * sub]);
                    S[sub][ntl][2] = ex2f(S[sub][ntl][2] - m[2 * sub + 1]);
                    S[sub][ntl][3] = ex2f(S[sub][ntl][3] - m[2 * sub + 1]);
                    sums[2 * sub]     += S[sub][ntl][0] + S[sub][ntl][1];
                    sums[2 * sub + 1] += S[sub][ntl][2] + S[sub][ntl][3];
                }
            }
            #pragma unroll
            for (int i = 0; i < 4; i++) {
                sums[i] += __shfl_xor_sync(0xffffffffu, sums[i], 1);
                sums[i] += __shfl_xor_sync(0xffffffffu, sums[i], 2);
                l[i] = l[i] * al[i] + sums[i];
            }
            #pragma unroll
            for (int sub = 0; sub < 2; sub++)
                #pragma unroll
                for (int no = 0; no < 4; no++) {
                    accO[sub][no][0] *= al[2 * sub];     accO[sub][no][1] *= al[2 * sub];
                    accO[sub][no][2] *= al[2 * sub + 1]; accO[sub][no][3] *= al[2 * sub + 1];
                }
            // --- O += P V over this half ---
            #pragma unroll
            for (int jl = 0; jl < 4; jl++) {
                uint32_t a[2][4];
                #pragma unroll
                for (int sub = 0; sub < 2; sub++) {
                    a[sub][0] = pack_bf16(S[sub][2 * jl][0],     S[sub][2 * jl][1]);
                    a[sub][1] = pack_bf16(S[sub][2 * jl][2],     S[sub][2 * jl][3]);
                    a[sub][2] = pack_bf16(S[sub][2 * jl + 1][0], S[sub][2 * jl + 1][1]);
                    a[sub][3] = pack_bf16(S[sub][2 * jl + 1][2], S[sub][2 * jl + 1][3]);
                }
                #pragma unroll
                for (int nob = 0; nob < 4; nob += 2) {
                    uint32_t v0, v1, v2, v3;
                    ldsm_x4t(v0, v1, v2, v3,
                             addrV + (half * 4 + jl) * (16 * KV_PITCH) + nob * 16);
                    #pragma unroll
                    for (int sub = 0; sub < 2; sub++) {
                        mma_bf16(accO[sub][nob][0], accO[sub][nob][1],
                                 accO[sub][nob][2], accO[sub][nob][3],
                                 a[sub][0], a[sub][1], a[sub][2], a[sub][3], v0, v1);
                        mma_bf16(accO[sub][nob + 1][0], accO[sub][nob + 1][1],
                                 accO[sub][nob + 1][2], accO[sub][nob + 1][3],
                                 a[sub][0], a[sub][1], a[sub][2], a[sub][3], v2, v3);
                    }
                }
            }
        }
        __syncthreads();
    }

    #pragma unroll
    for (int sub = 0; sub < 2; sub++) {
        float il = 1.f / l[2 * sub];
        float ih = 1.f / l[2 * sub + 1];
        if (r[2 * sub] < NSEQ) {
            #pragma unroll
            for (int no = 0; no < 4; no++) {
                float2 v = make_float2(accO[sub][no][0] * il, accO[sub][no][1] * il);
                *(float2*)&g_att[((size_t)b * NSEQ + r[2 * sub]) * 256 + h * 32 + no * 8 + 2 * t] = v;
            }
        }
        if (r[2 * sub + 1] < NSEQ) {
            #pragma unroll
            for (int no = 0; no < 4; no++) {
                float2 v = make_float2(accO[sub][no][2] * ih, accO[sub][no][3] * ih);
                *(float2*)&g_att[((size_t)b * NSEQ + r[2 * sub + 1]) * 256 + h * 32 + no * 8 + 2 * t] = v;
            }
        }
    }
}

// ---------------- launch ----------------
extern "C" void kernel_launch(void* const* d_in, const int* in_sizes, int n_in,
                              void* d_out, int out_size) {
    const float*         x       = (const float*)d_in[0];
    const unsigned char* mask    = (const unsigned char*)d_in[1];
    const float*         w_qkv   = (const float*)d_in[2];
    const float*         w_proj  = (const float*)d_in[3];
    const float*         b_proj  = (const float*)d_in[4];
    const float*         rpb     = (const float*)d_in[5];
    const int*           relidx  = (const int*)d_in[6];
    const int num_rel = in_sizes[5] / H_;

    const int GEMM_SMEM = 2 * 128 * 68 * 4;           // 69632
    cudaFuncSetAttribute(gemm_tf32<0>, cudaFuncAttributeMaxDynamicSharedMemorySize, GEMM_SMEM);
    cudaFuncSetAttribute(gemm_tf32<1>, cudaFuncAttributeMaxDynamicSharedMemorySize, GEMM_SMEM);
    cudaFuncSetAttribute(attn_kernel,  cudaFuncAttributeMaxDynamicSharedMemorySize, ATTN_SMEM);

    void* p_att = nullptr;
    cudaGetSymbolAddress(&p_att, g_att);

    mask_kernel<<<1, 256>>>(mask);
    bias_kernel<<<(NSEQ * NPAD + 255) / 256, 256>>>(relidx, rpb, num_rel);
    gemm_tf32<0><<<dim3(MROWS / 128, 768 / 128), 256, GEMM_SMEM>>>(
        x, w_qkv, nullptr, nullptr, 768);
    attn_kernel<<<dim3(10, B_ * H_), 128, ATTN_SMEM>>>();
    gemm_tf32<1><<<dim3(MROWS / 128, 256 / 128), 256, GEMM_SMEM>>>(
        (const float*)p_att, w_proj, b_proj, (float*)d_out, 256);
}